// round 5
// baseline (speedup 1.0000x reference)
#include <cuda_runtime.h>
#include <cuda_bf16.h>
#include <cstdint>
#include <cstddef>
#include <math.h>

// ---------------- problem constants (fixed by setup_inputs) ----------------
#define BATCH   2
#define TMOT    1024
#define DMODEL  1024
#define LSEQ    5632        // 3*TMOT + 5*NTXT
#define DIN     4096
#define DSTATE  128
#define DTRANK  64
#define HID     4096
#define NTXT    512
#define XDBLW   320         // dt_rank + 2*d_state
#define NHEAD   3
#define NGRP    5

typedef __nv_bfloat16 bf16;

// ---------------- scratch (static device globals; no allocation) -----------
// fp32 intermediates
__device__ float g_xz  [NHEAD*2048*8192];    // in_proj out (xi|z)
__device__ float g_xc  [NHEAD*2048*4096];    // conv+silu (scan u)
__device__ float g_xdbl[NHEAD*2048*320];     // x_proj out (dt|B|C) for scan
__device__ float g_dt  [NHEAD*2048*4096];    // dt_proj out -> softplus
__device__ float g_mot [NHEAD*2048*1024];    // out_proj result
__device__ float g_negA[NHEAD*4096*128];     // -exp(A_log)
__device__ float g_gb  [5120*4096];          // mlp gate (pre-act)
__device__ float g_ub  [5120*4096];          // mlp up
__device__ float g_txt [5120*1024];          // mlp down result
// bf16 hi/lo planes (GEMM operands)
__device__ bf16 g_xnh [NHEAD*2048*1024],  g_xnl [NHEAD*2048*1024];
__device__ bf16 g_xch [NHEAD*2048*4096],  g_xcl [NHEAD*2048*4096];
__device__ bf16 g_xdh [NHEAD*2048*320],   g_xdl [NHEAD*2048*320];
__device__ bf16 g_ymh [NHEAD*2048*4096],  g_yml [NHEAD*2048*4096];
__device__ bf16 g_tnh [5120*1024],        g_tnl [5120*1024];
__device__ bf16 g_gbh [5120*4096],        g_gbl [5120*4096];
// weight planes
__device__ bf16 g_wih [NHEAD*8192*1024],  g_wil [NHEAD*8192*1024];
__device__ bf16 g_wxh [NHEAD*320*4096],   g_wxl [NHEAD*320*4096];
__device__ bf16 g_wdth[NHEAD*4096*64],    g_wdtl[NHEAD*4096*64];
__device__ bf16 g_woh [NHEAD*1024*4096],  g_wol [NHEAD*1024*4096];
__device__ bf16 g_wgh [4096*1024],        g_wgl [4096*1024];
__device__ bf16 g_wuh [4096*1024],        g_wul [4096*1024];
__device__ bf16 g_wdh [1024*4096],        g_wdl [1024*4096];

__device__ __forceinline__ void split_store(float v, bf16* hi, bf16* lo, long i) {
    bf16 h = __float2bfloat16(v);
    hi[i] = h;
    lo[i] = __float2bfloat16(v - __bfloat162float(h));
}

// ===================== bf16x3 tensor-core GEMM (pre-split operands) =========
// C[M,N] = A[M,K] @ B[N,K]^T ; A = Ah+Al, B = Bh+Bl ; D += AhBh + AhBl + AlBh
// 128x128 CTA tile, BK=32, 8 warps (2x4, 64x32 each), 3-stage cp.async pipe,
// 80B-padded smem rows (conflict-free ldmatrix).

#define GBM 128
#define GBN 128
#define GBK 32
#define STAGES 3
#define ROWB   80
#define PLANEB (128 * ROWB)        // 10240 B
#define STAGEB (4 * PLANEB)        // 40960 B: Ah, Al, Bh, Bl
#define GSMEM  (STAGES * STAGEB)   // 122880 B

__device__ __forceinline__ uint32_t smem_u32(const void* p) {
    return (uint32_t)__cvta_generic_to_shared(p);
}
__device__ __forceinline__ void cpasync16(uint32_t dst, const void* src, int sz) {
    asm volatile("cp.async.cg.shared.global [%0], [%1], 16, %2;"
                 :: "r"(dst), "l"(src), "r"(sz) : "memory");
}
__device__ __forceinline__ void cp_commit() {
    asm volatile("cp.async.commit_group;" ::: "memory");
}
template <int N>
__device__ __forceinline__ void cp_wait() {
    asm volatile("cp.async.wait_group %0;" :: "n"(N) : "memory");
}
__device__ __forceinline__ void ldsm4(uint32_t& r0, uint32_t& r1,
                                      uint32_t& r2, uint32_t& r3, uint32_t a) {
    asm volatile("ldmatrix.sync.aligned.m8n8.x4.shared.b16 {%0,%1,%2,%3}, [%4];"
                 : "=r"(r0), "=r"(r1), "=r"(r2), "=r"(r3) : "r"(a));
}
__device__ __forceinline__ void mma16816(float* c, uint32_t a0, uint32_t a1,
                                         uint32_t a2, uint32_t a3,
                                         uint32_t b0, uint32_t b1) {
    asm volatile(
        "mma.sync.aligned.m16n8k16.row.col.f32.bf16.bf16.f32 "
        "{%0,%1,%2,%3}, {%4,%5,%6,%7}, {%8,%9}, {%0,%1,%2,%3};"
        : "+f"(c[0]), "+f"(c[1]), "+f"(c[2]), "+f"(c[3])
        : "r"(a0), "r"(a1), "r"(a2), "r"(a3), "r"(b0), "r"(b1));
}

__global__ __launch_bounds__(256, 1) void gemm_mma(
    const bf16* __restrict__ Ahi, const bf16* __restrict__ Alo, int lda, long sA,
    const bf16* __restrict__ Bhi, const bf16* __restrict__ Blo, int ldb, long sB,
    float* __restrict__ C, int ldc, long sC,
    bf16* __restrict__ Chi, bf16* __restrict__ Clo, long sCp,
    int M, int N, int K)
{
    extern __shared__ char dsm[];
    Ahi += (long)blockIdx.z * sA;  Alo += (long)blockIdx.z * sA;
    Bhi += (long)blockIdx.z * sB;  Blo += (long)blockIdx.z * sB;
    C   += (long)blockIdx.z * sC;

    const int tid  = threadIdx.x;
    const int wid  = tid >> 5;
    const int lane = tid & 31;
    const int bm = blockIdx.y * GBM;
    const int bn = blockIdx.x * GBN;
    const int wm = wid >> 2;          // 0..1
    const int wn = wid & 3;           // 0..3

    // loader mapping: thread -> (row, 32B half)
    const int r  = tid >> 1;
    const int hf = tid & 1;
    const bf16* pAh = Ahi + (long)(bm + r) * lda + hf * 16;
    const bf16* pAl = Alo + (long)(bm + r) * lda + hf * 16;
    const bf16* pBh = Bhi + (long)(bn + r) * ldb + hf * 16;
    const bf16* pBl = Blo + (long)(bn + r) * ldb + hf * 16;
    const int bsz = ((bn + r) < N) ? 16 : 0;
    const uint32_t soff = (uint32_t)(r * ROWB + hf * 32);
    const uint32_t sm0 = smem_u32(dsm);

    const int nch = K / GBK;

    auto issue = [&](int c, int st) {
        const int k0 = c * GBK;
        const uint32_t sb = sm0 + st * STAGEB + soff;
        cpasync16(sb + 0 * PLANEB,      pAh + k0,     16);
        cpasync16(sb + 0 * PLANEB + 16, pAh + k0 + 8, 16);
        cpasync16(sb + 1 * PLANEB,      pAl + k0,     16);
        cpasync16(sb + 1 * PLANEB + 16, pAl + k0 + 8, 16);
        cpasync16(sb + 2 * PLANEB,      pBh + k0,     bsz);
        cpasync16(sb + 2 * PLANEB + 16, pBh + k0 + 8, bsz);
        cpasync16(sb + 3 * PLANEB,      pBl + k0,     bsz);
        cpasync16(sb + 3 * PLANEB + 16, pBl + k0 + 8, bsz);
        cp_commit();
    };

    float acc[4][4][4];
    #pragma unroll
    for (int i = 0; i < 4; i++)
        #pragma unroll
        for (int j = 0; j < 4; j++)
            #pragma unroll
            for (int q = 0; q < 4; q++) acc[i][j][q] = 0.f;

    const uint32_t lmoff = (uint32_t)((lane & 15) * ROWB + (lane >> 4) * 16);

    const int npro = (nch < STAGES - 1) ? nch : (STAGES - 1);
    for (int s = 0; s < npro; s++) issue(s, s);

    for (int c = 0; c < nch; c++) {
        if (c + STAGES - 1 < nch) cp_wait<1>();
        else                      cp_wait<0>();
        __syncthreads();
        if (c + STAGES - 1 < nch) issue(c + STAGES - 1, (c + STAGES - 1) % STAGES);

        const uint32_t sb = sm0 + (c % STAGES) * STAGEB;
        const uint32_t aH = sb + (uint32_t)(wm * 64 * ROWB) + lmoff;
        const uint32_t bH = sb + 2u * PLANEB + (uint32_t)(wn * 32 * ROWB) + lmoff;
        #pragma unroll
        for (int ks = 0; ks < 2; ks++) {
            const uint32_t ko = ks * 32;   // 16 bf16 = 32 B
            uint32_t Ah[4][4], Al[4][4], Bh[4][2], Bl[4][2];
            #pragma unroll
            for (int mt = 0; mt < 4; mt++) {
                ldsm4(Ah[mt][0], Ah[mt][1], Ah[mt][2], Ah[mt][3],
                      aH + mt * 16 * ROWB + ko);
                ldsm4(Al[mt][0], Al[mt][1], Al[mt][2], Al[mt][3],
                      aH + PLANEB + mt * 16 * ROWB + ko);
            }
            #pragma unroll
            for (int p = 0; p < 2; p++) {
                uint32_t r0, r1, r2, r3;
                ldsm4(r0, r1, r2, r3, bH + p * 16 * ROWB + ko);
                Bh[2*p][0] = r0; Bh[2*p+1][0] = r1;
                Bh[2*p][1] = r2; Bh[2*p+1][1] = r3;
                ldsm4(r0, r1, r2, r3, bH + PLANEB + p * 16 * ROWB + ko);
                Bl[2*p][0] = r0; Bl[2*p+1][0] = r1;
                Bl[2*p][1] = r2; Bl[2*p+1][1] = r3;
            }
            #pragma unroll
            for (int mt = 0; mt < 4; mt++)
                #pragma unroll
                for (int nt = 0; nt < 4; nt++) {
                    mma16816(acc[mt][nt], Ah[mt][0], Ah[mt][1], Ah[mt][2],
                             Ah[mt][3], Bh[nt][0], Bh[nt][1]);
                    mma16816(acc[mt][nt], Ah[mt][0], Ah[mt][1], Ah[mt][2],
                             Ah[mt][3], Bl[nt][0], Bl[nt][1]);
                    mma16816(acc[mt][nt], Al[mt][0], Al[mt][1], Al[mt][2],
                             Al[mt][3], Bh[nt][0], Bh[nt][1]);
                }
        }
        __syncthreads();
    }

    // ---- epilogue: fp32 C, optional bf16 hi/lo planes ----
    bf16* ChiB = Chi ? Chi + (long)blockIdx.z * sCp : nullptr;
    bf16* CloB = Clo ? Clo + (long)blockIdx.z * sCp : nullptr;
    #pragma unroll
    for (int mt = 0; mt < 4; mt++) {
        const int row0 = bm + wm * 64 + mt * 16 + (lane >> 2);
        #pragma unroll
        for (int nt = 0; nt < 4; nt++) {
            const int col = bn + wn * 32 + nt * 8 + (lane & 3) * 2;
            if (col < N) {
                *(float2*)(C + (long)row0 * ldc + col) =
                    make_float2(acc[mt][nt][0], acc[mt][nt][1]);
                *(float2*)(C + (long)(row0 + 8) * ldc + col) =
                    make_float2(acc[mt][nt][2], acc[mt][nt][3]);
                if (ChiB) {
                    split_store(acc[mt][nt][0], ChiB, CloB, (long)row0 * ldc + col);
                    split_store(acc[mt][nt][1], ChiB, CloB, (long)row0 * ldc + col + 1);
                    split_store(acc[mt][nt][2], ChiB, CloB, (long)(row0 + 8) * ldc + col);
                    split_store(acc[mt][nt][3], ChiB, CloB, (long)(row0 + 8) * ldc + col + 1);
                }
            }
        }
    }
}

// ---------------- weight fp32 -> hi/lo bf16 split ----------------
__global__ void convert_split_kernel(const float* __restrict__ src,
                                     bf16* __restrict__ hi, bf16* __restrict__ lo,
                                     int n) {
    int i = blockIdx.x * 256 + threadIdx.x;
    if (i < n) split_store(src[i], hi, lo, i);
}

// ---------------- rmsnorm ----------------
__device__ __forceinline__ float block_sum256(float v, float* sh) {
    #pragma unroll
    for (int o = 16; o; o >>= 1) v += __shfl_xor_sync(0xffffffffu, v, o);
    if ((threadIdx.x & 31) == 0) sh[threadIdx.x >> 5] = v;
    __syncthreads();
    float tot = 0.f;
    #pragma unroll
    for (int i = 0; i < 8; i++) tot += sh[i];
    return tot;
}

__global__ __launch_bounds__(256) void rms_motion_kernel(
    const float* __restrict__ x, const float* __restrict__ w)
{
    __shared__ float sh[8];
    int t = blockIdx.x, b = blockIdx.y, h = blockIdx.z;
    const float4* row = (const float4*)(x + ((long)b * LSEQ + h * TMOT + t) * DMODEL);
    const float4* wr  = (const float4*)(w + h * DMODEL);
    long obase = ((long)(h * 2 + b) * TMOT + t) * DMODEL + threadIdx.x * 4;
    float4 v = row[threadIdx.x];
    float tot = block_sum256(v.x*v.x + v.y*v.y + v.z*v.z + v.w*v.w, sh);
    float s = rsqrtf(tot * (1.f / DMODEL) + 1e-6f);
    float4 wv = wr[threadIdx.x];
    split_store(v.x * s * wv.x, g_xnh, g_xnl, obase + 0);
    split_store(v.y * s * wv.y, g_xnh, g_xnl, obase + 1);
    split_store(v.z * s * wv.z, g_xnh, g_xnl, obase + 2);
    split_store(v.w * s * wv.w, g_xnh, g_xnl, obase + 3);
}

__global__ __launch_bounds__(256) void rms_text_kernel(
    const float* __restrict__ x, const float* __restrict__ w)
{
    __shared__ float sh[8];
    int n = blockIdx.x, b = blockIdx.y, g = blockIdx.z;
    const float4* row = (const float4*)(x + ((long)b * LSEQ + 3 * TMOT + g * NTXT + n) * DMODEL);
    const float4* wr  = (const float4*)(w + g * DMODEL);
    long obase = ((long)(g * 2 + b) * NTXT + n) * DMODEL + threadIdx.x * 4;
    float4 v = row[threadIdx.x];
    float tot = block_sum256(v.x*v.x + v.y*v.y + v.z*v.z + v.w*v.w, sh);
    float s = rsqrtf(tot * (1.f / DMODEL) + 1e-6f);
    float4 wv = wr[threadIdx.x];
    split_store(v.x * s * wv.x, g_tnh, g_tnl, obase + 0);
    split_store(v.y * s * wv.y, g_tnh, g_tnl, obase + 1);
    split_store(v.z * s * wv.z, g_tnh, g_tnl, obase + 2);
    split_store(v.w * s * wv.w, g_tnh, g_tnl, obase + 3);
}

// ---------------- elementwise stages ----------------
__global__ void negA_kernel(const float* __restrict__ A_log) {
    int i = blockIdx.x * 256 + threadIdx.x;
    if (i < NHEAD * DIN * DSTATE) g_negA[i] = -expf(A_log[i]);
}

// depthwise causal conv (D_CONV=4) + bias + silu ; xi = first half of xz rows
__global__ void conv_silu_kernel(const float* __restrict__ cw, const float* __restrict__ cb) {
    int idx = blockIdx.x * 256 + threadIdx.x;
    if (idx >= NHEAD * 2 * TMOT * DIN) return;
    int d  = idx & (DIN - 1);
    int r  = idx >> 12;             // (h*2+b)*1024 + t
    int t  = r & (TMOT - 1);
    int hb = r >> 10;
    int h  = hb >> 1;
    const float* xi  = g_xz + (long)hb * TMOT * 8192 + d;    // row stride 2*din
    const float* cwd = cw + ((long)h * DIN + d) * 4;
    float acc = cb[h * DIN + d];
    #pragma unroll
    for (int k = 0; k < 4; k++) {
        int ti = t - 3 + k;
        if (ti >= 0) acc += xi[(long)ti * 8192] * cwd[k];
    }
    float v = acc / (1.f + __expf(-acc));
    g_xc[idx] = v;
    split_store(v, g_xch, g_xcl, idx);
}

__global__ void dt_act_kernel(const float* __restrict__ bias) {
    int idx = blockIdx.x * 256 + threadIdx.x;
    if (idx >= NHEAD * 2048 * DIN) return;
    int n = idx & (DIN - 1);
    int h = idx / (2048 * DIN);
    float v = g_dt[idx] + bias[h * DIN + n];
    g_dt[idx] = (v > 20.f) ? v : log1pf(__expf(v));
}

__global__ void silu_gate_kernel() {
    int idx = blockIdx.x * 256 + threadIdx.x;
    if (idx >= 5120 * HID) return;
    float g = g_gb[idx];
    float v = g / (1.f + __expf(-g)) * g_ub[idx];
    split_store(v, g_gbh, g_gbl, idx);
}

__global__ void scatter_motion_kernel(const float* __restrict__ x, float* __restrict__ out) {
    int idx = blockIdx.x * 256 + threadIdx.x;
    if (idx >= NHEAD * 2 * TMOT * DMODEL) return;
    int d  = idx & (DMODEL - 1);
    int r  = idx >> 10;
    int t  = r & (TMOT - 1);
    int hb = r >> 10;
    int h = hb >> 1, b = hb & 1;
    long o = ((long)b * LSEQ + h * TMOT + t) * DMODEL + d;
    out[o] = x[o] + g_mot[idx];
}

__global__ void scatter_text_kernel(const float* __restrict__ x, float* __restrict__ out) {
    int idx = blockIdx.x * 256 + threadIdx.x;
    if (idx >= NGRP * 2 * NTXT * DMODEL) return;
    int d  = idx & (DMODEL - 1);
    int r  = idx >> 10;
    int n  = r & (NTXT - 1);
    int gb = r >> 9;
    int g = gb >> 1, b = gb & 1;
    long o = ((long)b * LSEQ + 3 * TMOT + g * NTXT + n) * DMODEL + d;
    out[o] = x[o] + g_txt[idx];
}

// ---------------- selective scan: warp per (h,b,d), 4 states per lane ------
__global__ __launch_bounds__(256) void scan_kernel(const float* __restrict__ Dp) {
    int h = blockIdx.z, b = blockIdx.y;
    int warp = threadIdx.x >> 5, lane = threadIdx.x & 31;
    int d = blockIdx.x * 8 + warp;
    long hb = h * 2 + b;
    const float* dt_p = g_dt + hb * TMOT * (long)DIN + d;
    const float* u_p  = g_xc + hb * TMOT * (long)DIN + d;
    const float* bc_p = g_xdbl + hb * TMOT * (long)XDBLW;
    const float* z_p  = g_xz + hb * TMOT * 8192L + DIN + d;
    const float* A_p  = g_negA + ((long)h * DIN + d) * DSTATE + lane * 4;
    float a0 = A_p[0], a1 = A_p[1], a2 = A_p[2], a3 = A_p[3];
    float Dv = Dp[h * DIN + d];
    long ybase = hb * TMOT * (long)DIN + d;

    float h0 = 0.f, h1 = 0.f, h2 = 0.f, h3 = 0.f;
    for (int t = 0; t < TMOT; t++) {
        float dtv = __ldg(dt_p + (long)t * DIN);
        float uv  = __ldg(u_p  + (long)t * DIN);
        float4 Bv = *(const float4*)(bc_p + (long)t * XDBLW + DTRANK + lane * 4);
        float4 Cv = *(const float4*)(bc_p + (long)t * XDBLW + DTRANK + DSTATE + lane * 4);
        float du = dtv * uv;
        h0 = h0 * __expf(dtv * a0) + du * Bv.x;
        h1 = h1 * __expf(dtv * a1) + du * Bv.y;
        h2 = h2 * __expf(dtv * a2) + du * Bv.z;
        h3 = h3 * __expf(dtv * a3) + du * Bv.w;
        float p = h0 * Cv.x + h1 * Cv.y + h2 * Cv.z + h3 * Cv.w;
        p += __shfl_xor_sync(0xffffffffu, p, 16);
        p += __shfl_xor_sync(0xffffffffu, p, 8);
        p += __shfl_xor_sync(0xffffffffu, p, 4);
        p += __shfl_xor_sync(0xffffffffu, p, 2);
        p += __shfl_xor_sync(0xffffffffu, p, 1);
        if (lane == 0) {
            float y  = p + uv * Dv;
            float zv = __ldg(z_p + (long)t * 8192);
            float yo = y * zv / (1.f + __expf(-zv));
            split_store(yo, g_ymh, g_yml, ybase + (long)t * DIN);
        }
    }
}

// ---------------- host orchestration ----------------
static inline int cdiv(int a, int b) { return (a + b - 1) / b; }

extern "C" void kernel_launch(void* const* d_in, const int* in_sizes, int n_in,
                              void* d_out, int out_size)
{
    const float* x     = (const float*)d_in[0];
    const float* nmw   = (const float*)d_in[3];
    const float* ntw   = (const float*)d_in[4];
    const float* w_in  = (const float*)d_in[5];
    const float* cw    = (const float*)d_in[6];
    const float* cb    = (const float*)d_in[7];
    const float* w_x   = (const float*)d_in[8];
    const float* w_dt  = (const float*)d_in[9];
    const float* b_dt  = (const float*)d_in[10];
    const float* A_log = (const float*)d_in[11];
    const float* Dp    = (const float*)d_in[12];
    const float* w_out = (const float*)d_in[13];
    const float* wg    = (const float*)d_in[14];
    const float* wu    = (const float*)d_in[15];
    const float* wd    = (const float*)d_in[16];
    float* out = (float*)d_out;

    float *xz, *xc, *xdbl, *dtb, *mot, *gb, *ub, *txt;
    bf16 *xnh, *xnl, *xch, *xcl, *xdh, *xdl, *ymh, *yml, *tnh, *tnl, *gbh, *gbl;
    bf16 *wih, *wil, *wxh, *wxl, *wdth, *wdtl, *woh, *wol,
         *wgh, *wgl, *wuh, *wul, *wdh, *wdl;
    cudaGetSymbolAddress((void**)&xz,   g_xz);
    cudaGetSymbolAddress((void**)&xc,   g_xc);
    cudaGetSymbolAddress((void**)&xdbl, g_xdbl);
    cudaGetSymbolAddress((void**)&dtb,  g_dt);
    cudaGetSymbolAddress((void**)&mot,  g_mot);
    cudaGetSymbolAddress((void**)&gb,   g_gb);
    cudaGetSymbolAddress((void**)&ub,   g_ub);
    cudaGetSymbolAddress((void**)&txt,  g_txt);
    cudaGetSymbolAddress((void**)&xnh,  g_xnh);  cudaGetSymbolAddress((void**)&xnl, g_xnl);
    cudaGetSymbolAddress((void**)&xch,  g_xch);  cudaGetSymbolAddress((void**)&xcl, g_xcl);
    cudaGetSymbolAddress((void**)&xdh,  g_xdh);  cudaGetSymbolAddress((void**)&xdl, g_xdl);
    cudaGetSymbolAddress((void**)&ymh,  g_ymh);  cudaGetSymbolAddress((void**)&yml, g_yml);
    cudaGetSymbolAddress((void**)&tnh,  g_tnh);  cudaGetSymbolAddress((void**)&tnl, g_tnl);
    cudaGetSymbolAddress((void**)&gbh,  g_gbh);  cudaGetSymbolAddress((void**)&gbl, g_gbl);
    cudaGetSymbolAddress((void**)&wih,  g_wih);  cudaGetSymbolAddress((void**)&wil, g_wil);
    cudaGetSymbolAddress((void**)&wxh,  g_wxh);  cudaGetSymbolAddress((void**)&wxl, g_wxl);
    cudaGetSymbolAddress((void**)&wdth, g_wdth); cudaGetSymbolAddress((void**)&wdtl, g_wdtl);
    cudaGetSymbolAddress((void**)&woh,  g_woh);  cudaGetSymbolAddress((void**)&wol, g_wol);
    cudaGetSymbolAddress((void**)&wgh,  g_wgh);  cudaGetSymbolAddress((void**)&wgl, g_wgl);
    cudaGetSymbolAddress((void**)&wuh,  g_wuh);  cudaGetSymbolAddress((void**)&wul, g_wul);
    cudaGetSymbolAddress((void**)&wdh,  g_wdh);  cudaGetSymbolAddress((void**)&wdl, g_wdl);

    cudaFuncSetAttribute(gemm_mma,
                         cudaFuncAttributeMaxDynamicSharedMemorySize, GSMEM);

    // ---- weight splits (cheap; every launch) ----
    {
        int n;
        n = NHEAD * 8192 * 1024;
        convert_split_kernel<<<cdiv(n, 256), 256>>>(w_in, wih, wil, n);
        n = NHEAD * 320 * 4096;
        convert_split_kernel<<<cdiv(n, 256), 256>>>(w_x, wxh, wxl, n);
        n = NHEAD * 4096 * 64;
        convert_split_kernel<<<cdiv(n, 256), 256>>>(w_dt, wdth, wdtl, n);
        n = NHEAD * 1024 * 4096;
        convert_split_kernel<<<cdiv(n, 256), 256>>>(w_out, woh, wol, n);
        n = 4096 * 1024;
        convert_split_kernel<<<cdiv(n, 256), 256>>>(wg, wgh, wgl, n);
        convert_split_kernel<<<cdiv(n, 256), 256>>>(wu, wuh, wul, n);
        convert_split_kernel<<<cdiv(n, 256), 256>>>(wd, wdh, wdl, n);
    }

    // ---- motion path ----
    negA_kernel<<<cdiv(NHEAD * DIN * DSTATE, 256), 256>>>(A_log);
    rms_motion_kernel<<<dim3(TMOT, BATCH, NHEAD), 256>>>(x, nmw);

    // in_proj: (2048x1024) @ (8192x1024)^T per head
    gemm_mma<<<dim3(8192 / GBN, 2048 / GBM, NHEAD), 256, GSMEM>>>(
        xnh, xnl, 1024, 2048L * 1024, wih, wil, 1024, 8192L * 1024,
        xz, 8192, 2048L * 8192, (bf16*)nullptr, (bf16*)nullptr, 0,
        2048, 8192, 1024);

    conv_silu_kernel<<<cdiv(NHEAD * 2 * TMOT * DIN, 256), 256>>>(cw, cb);

    // x_proj: (2048x4096) @ (320x4096)^T -> fp32 + hi/lo planes
    gemm_mma<<<dim3(3, 2048 / GBM, NHEAD), 256, GSMEM>>>(
        xch, xcl, DIN, 2048L * DIN, wxh, wxl, DIN, (long)XDBLW * DIN,
        xdbl, XDBLW, 2048L * XDBLW, xdh, xdl, 2048L * XDBLW,
        2048, XDBLW, DIN);

    // dt_proj: (2048x64) @ (4096x64)^T (A = first 64 cols of xdbl planes)
    gemm_mma<<<dim3(DIN / GBN, 2048 / GBM, NHEAD), 256, GSMEM>>>(
        xdh, xdl, XDBLW, 2048L * XDBLW, wdth, wdtl, DTRANK, (long)DIN * DTRANK,
        dtb, DIN, 2048L * DIN, (bf16*)nullptr, (bf16*)nullptr, 0,
        2048, DIN, DTRANK);

    dt_act_kernel<<<cdiv(NHEAD * 2048 * DIN, 256), 256>>>(b_dt);

    scan_kernel<<<dim3(DIN / 8, BATCH, NHEAD), 256>>>(Dp);

    // out_proj: (2048x4096) @ (1024x4096)^T
    gemm_mma<<<dim3(DMODEL / GBN, 2048 / GBM, NHEAD), 256, GSMEM>>>(
        ymh, yml, DIN, 2048L * DIN, woh, wol, DIN, (long)DMODEL * DIN,
        mot, DMODEL, 2048L * DMODEL, (bf16*)nullptr, (bf16*)nullptr, 0,
        2048, DMODEL, DIN);

    scatter_motion_kernel<<<cdiv(NHEAD * 2 * TMOT * DMODEL, 256), 256>>>(x, out);

    // ---- text path ----
    rms_text_kernel<<<dim3(NTXT, BATCH, NGRP), 256>>>(x, ntw);

    gemm_mma<<<dim3(HID / GBN, 5120 / GBM, 1), 256, GSMEM>>>(
        tnh, tnl, DMODEL, 0, wgh, wgl, DMODEL, 0,
        gb, HID, 0, (bf16*)nullptr, (bf16*)nullptr, 0,
        5120, HID, DMODEL);
    gemm_mma<<<dim3(HID / GBN, 5120 / GBM, 1), 256, GSMEM>>>(
        tnh, tnl, DMODEL, 0, wuh, wul, DMODEL, 0,
        ub, HID, 0, (bf16*)nullptr, (bf16*)nullptr, 0,
        5120, HID, DMODEL);

    silu_gate_kernel<<<cdiv(5120 * HID, 256), 256>>>();

    gemm_mma<<<dim3(DMODEL / GBN, 5120 / GBM, 1), 256, GSMEM>>>(
        gbh, gbl, HID, 0, wdh, wdl, HID, 0,
        txt, DMODEL, 0, (bf16*)nullptr, (bf16*)nullptr, 0,
        5120, DMODEL, HID);

    scatter_text_kernel<<<cdiv(NGRP * 2 * NTXT * DMODEL, 256), 256>>>(x, out);
}

// round 6
// speedup vs baseline: 1.0682x; 1.0682x over previous
#include <cuda_runtime.h>
#include <cuda_bf16.h>
#include <cstdint>
#include <cstddef>
#include <math.h>

// ---------------- problem constants (fixed by setup_inputs) ----------------
#define BATCH   2
#define TMOT    1024
#define DMODEL  1024
#define LSEQ    5632        // 3*TMOT + 5*NTXT
#define DIN     4096
#define DSTATE  128
#define DTRANK  64
#define HID     4096
#define NTXT    512
#define XDBLW   320         // dt_rank + 2*d_state
#define NHEAD   3
#define NGRP    5

typedef __nv_bfloat16 bf16;

// ---------------- scratch (static device globals; no allocation) -----------
// fp32 intermediates
__device__ float g_xz  [NHEAD*2048*8192];    // in_proj out (xi|z)
__device__ float g_xc  [NHEAD*2048*4096];    // conv+silu (scan u)
__device__ float g_xdbl[NHEAD*2048*320];     // x_proj out (dt|B|C) for scan
__device__ float g_dt  [NHEAD*2048*4096];    // dt_proj out -> softplus
__device__ float g_mot [NHEAD*2048*1024];    // out_proj result
__device__ float g_negA[NHEAD*4096*128];     // -exp(A_log)
__device__ float g_gb  [5120*4096];          // mlp gate (pre-act)
__device__ float g_ub  [5120*4096];          // mlp up
__device__ float g_txt [5120*1024];          // mlp down result
// bf16 hi/lo planes (GEMM operands)
__device__ bf16 g_xnh [NHEAD*2048*1024],  g_xnl [NHEAD*2048*1024];
__device__ bf16 g_xch [NHEAD*2048*4096],  g_xcl [NHEAD*2048*4096];
__device__ bf16 g_xdh [NHEAD*2048*320],   g_xdl [NHEAD*2048*320];
__device__ bf16 g_ymh [NHEAD*2048*4096],  g_yml [NHEAD*2048*4096];
__device__ bf16 g_tnh [5120*1024],        g_tnl [5120*1024];
__device__ bf16 g_gbh [5120*4096],        g_gbl [5120*4096];
// weight planes
__device__ bf16 g_wih [NHEAD*8192*1024],  g_wil [NHEAD*8192*1024];
__device__ bf16 g_wxh [NHEAD*320*4096],   g_wxl [NHEAD*320*4096];
__device__ bf16 g_wdth[NHEAD*4096*64],    g_wdtl[NHEAD*4096*64];
__device__ bf16 g_woh [NHEAD*1024*4096],  g_wol [NHEAD*1024*4096];
__device__ bf16 g_wgh [4096*1024],        g_wgl [4096*1024];
__device__ bf16 g_wuh [4096*1024],        g_wul [4096*1024];
__device__ bf16 g_wdh [1024*4096],        g_wdl [1024*4096];

__device__ __forceinline__ void split_store(float v, bf16* hi, bf16* lo, long i) {
    bf16 h = __float2bfloat16(v);
    hi[i] = h;
    lo[i] = __float2bfloat16(v - __bfloat162float(h));
}

// ===================== bf16x3 tensor-core GEMM (pre-split operands) =========
// C[M,N] = A[M,K] @ B[N,K]^T ; A = Ah+Al, B = Bh+Bl ; D += AhBh + AhBl + AlBh
// 128x128 CTA tile, BK=32, 8 warps (2x4, 64x32 each).
// Round-4-proven structure: reg-prefetch + double-buffered smem;
// only change: operands arrive pre-split (uint4 loads, no conversion).

#define GBM 128
#define GBN 128
#define GBK 32
#define ROWB    80                 // 32 bf16 (64B) + 16B pad
#define PLANEB  (128 * ROWB)       // 10240 B
#define STAGEB  (4 * PLANEB)       // Ah, Al, Bh, Bl = 40960 B
#define GSMEM   (2 * STAGEB)       // 81920 B

__device__ __forceinline__ uint32_t smem_u32(const void* p) {
    return (uint32_t)__cvta_generic_to_shared(p);
}
__device__ __forceinline__ void ldsm4(uint32_t& r0, uint32_t& r1,
                                      uint32_t& r2, uint32_t& r3, uint32_t a) {
    asm volatile("ldmatrix.sync.aligned.m8n8.x4.shared.b16 {%0,%1,%2,%3}, [%4];"
                 : "=r"(r0), "=r"(r1), "=r"(r2), "=r"(r3) : "r"(a));
}
__device__ __forceinline__ void mma16816(float* c, uint32_t a0, uint32_t a1,
                                         uint32_t a2, uint32_t a3,
                                         uint32_t b0, uint32_t b1) {
    asm volatile(
        "mma.sync.aligned.m16n8k16.row.col.f32.bf16.bf16.f32 "
        "{%0,%1,%2,%3}, {%4,%5,%6,%7}, {%8,%9}, {%0,%1,%2,%3};"
        : "+f"(c[0]), "+f"(c[1]), "+f"(c[2]), "+f"(c[3])
        : "r"(a0), "r"(a1), "r"(a2), "r"(a3), "r"(b0), "r"(b1));
}

__global__ __launch_bounds__(256, 1) void gemm_mma(
    const bf16* __restrict__ Ahi, const bf16* __restrict__ Alo, int lda, long sA,
    const bf16* __restrict__ Bhi, const bf16* __restrict__ Blo, int ldb, long sB,
    float* __restrict__ C, int ldc, long sC,
    bf16* __restrict__ Chi, bf16* __restrict__ Clo, long sCp,
    int M, int N, int K)
{
    extern __shared__ char dsm[];
    Ahi += (long)blockIdx.z * sA;  Alo += (long)blockIdx.z * sA;
    Bhi += (long)blockIdx.z * sB;  Blo += (long)blockIdx.z * sB;
    C   += (long)blockIdx.z * sC;

    const int tid  = threadIdx.x;
    const int wid  = tid >> 5;
    const int lane = tid & 31;
    const int bm = blockIdx.y * GBM;
    const int bn = blockIdx.x * GBN;
    const int wm = wid >> 2;          // 0..1
    const int wn = wid & 3;           // 0..3

    // loader mapping: thread -> (row, 16-col half); 32 bf16 = 64B per matrix row
    const int r  = tid >> 1;
    const int hf = tid & 1;
    const bf16* pAh = Ahi + (long)(bm + r) * lda + hf * 16;
    const bf16* pAl = Alo + (long)(bm + r) * lda + hf * 16;
    const bf16* pBh = Bhi + (long)(bn + r) * ldb + hf * 16;
    const bf16* pBl = Blo + (long)(bn + r) * ldb + hf * 16;
    const bool bok = (bn + r) < N;
    const uint32_t soff = (uint32_t)(r * ROWB + hf * 32);

    uint4 vAh[1], vAl[1], vBh[1], vBl[1];   // 16B each; 2 halves fetched as 2 regsets
    uint4 wAh, wAl, wBh, wBl;
    const int nch = K / GBK;

    auto fetch = [&](int c) {
        const int k0 = c * GBK;
        vAh[0] = *(const uint4*)(pAh + k0);
        wAh    = *(const uint4*)(pAh + k0 + 8);
        vAl[0] = *(const uint4*)(pAl + k0);
        wAl    = *(const uint4*)(pAl + k0 + 8);
        if (bok) {
            vBh[0] = *(const uint4*)(pBh + k0);
            wBh    = *(const uint4*)(pBh + k0 + 8);
            vBl[0] = *(const uint4*)(pBl + k0);
            wBl    = *(const uint4*)(pBl + k0 + 8);
        } else {
            vBh[0] = make_uint4(0,0,0,0); wBh = make_uint4(0,0,0,0);
            vBl[0] = make_uint4(0,0,0,0); wBl = make_uint4(0,0,0,0);
        }
    };
    auto store = [&](int st) {
        char* base = dsm + st * STAGEB;
        *(uint4*)(base + 0 * PLANEB + soff)      = vAh[0];
        *(uint4*)(base + 0 * PLANEB + soff + 16) = wAh;
        *(uint4*)(base + 1 * PLANEB + soff)      = vAl[0];
        *(uint4*)(base + 1 * PLANEB + soff + 16) = wAl;
        *(uint4*)(base + 2 * PLANEB + soff)      = vBh[0];
        *(uint4*)(base + 2 * PLANEB + soff + 16) = wBh;
        *(uint4*)(base + 3 * PLANEB + soff)      = vBl[0];
        *(uint4*)(base + 3 * PLANEB + soff + 16) = wBl;
    };

    float acc[4][4][4];
    #pragma unroll
    for (int i = 0; i < 4; i++)
        #pragma unroll
        for (int j = 0; j < 4; j++)
            #pragma unroll
            for (int q = 0; q < 4; q++) acc[i][j][q] = 0.f;

    const uint32_t lmoff = (uint32_t)((lane & 15) * ROWB + (lane >> 4) * 16);
    const uint32_t sm0 = smem_u32(dsm);

    // ---- prologue ----
    fetch(0);
    store(0);
    if (nch > 1) fetch(1);
    __syncthreads();

    for (int c = 0; c < nch; c++) {
        const uint32_t sb = sm0 + (c & 1) * STAGEB;
        const uint32_t aH = sb + (uint32_t)(wm * 64 * ROWB) + lmoff;
        const uint32_t bH = sb + 2u * PLANEB + (uint32_t)(wn * 32 * ROWB) + lmoff;
        #pragma unroll
        for (int ks = 0; ks < 2; ks++) {
            const uint32_t ko = ks * 32;   // 16 bf16 = 32 B
            uint32_t Ah[4][4], Al[4][4], Bh[4][2], Bl[4][2];
            #pragma unroll
            for (int mt = 0; mt < 4; mt++) {
                ldsm4(Ah[mt][0], Ah[mt][1], Ah[mt][2], Ah[mt][3],
                      aH + mt * 16 * ROWB + ko);
                ldsm4(Al[mt][0], Al[mt][1], Al[mt][2], Al[mt][3],
                      aH + PLANEB + mt * 16 * ROWB + ko);
            }
            #pragma unroll
            for (int p = 0; p < 2; p++) {
                uint32_t r0, r1, r2, r3;
                ldsm4(r0, r1, r2, r3, bH + p * 16 * ROWB + ko);
                Bh[2*p][0] = r0; Bh[2*p+1][0] = r1;
                Bh[2*p][1] = r2; Bh[2*p+1][1] = r3;
                ldsm4(r0, r1, r2, r3, bH + PLANEB + p * 16 * ROWB + ko);
                Bl[2*p][0] = r0; Bl[2*p+1][0] = r1;
                Bl[2*p][1] = r2; Bl[2*p+1][1] = r3;
            }
            #pragma unroll
            for (int mt = 0; mt < 4; mt++)
                #pragma unroll
                for (int nt = 0; nt < 4; nt++) {
                    mma16816(acc[mt][nt], Ah[mt][0], Ah[mt][1], Ah[mt][2],
                             Ah[mt][3], Bh[nt][0], Bh[nt][1]);
                    mma16816(acc[mt][nt], Ah[mt][0], Ah[mt][1], Ah[mt][2],
                             Ah[mt][3], Bl[nt][0], Bl[nt][1]);
                    mma16816(acc[mt][nt], Al[mt][0], Al[mt][1], Al[mt][2],
                             Al[mt][3], Bh[nt][0], Bh[nt][1]);
                }
        }
        if (c + 1 < nch) {
            store((c + 1) & 1);
            if (c + 2 < nch) fetch(c + 2);
        }
        __syncthreads();
    }

    // ---- epilogue: fp32 C, optional bf16 hi/lo planes ----
    bf16* ChiB = Chi ? Chi + (long)blockIdx.z * sCp : nullptr;
    bf16* CloB = Clo ? Clo + (long)blockIdx.z * sCp : nullptr;
    #pragma unroll
    for (int mt = 0; mt < 4; mt++) {
        const int row0 = bm + wm * 64 + mt * 16 + (lane >> 2);
        #pragma unroll
        for (int nt = 0; nt < 4; nt++) {
            const int col = bn + wn * 32 + nt * 8 + (lane & 3) * 2;
            if (col < N) {
                *(float2*)(C + (long)row0 * ldc + col) =
                    make_float2(acc[mt][nt][0], acc[mt][nt][1]);
                *(float2*)(C + (long)(row0 + 8) * ldc + col) =
                    make_float2(acc[mt][nt][2], acc[mt][nt][3]);
                if (ChiB) {
                    split_store(acc[mt][nt][0], ChiB, CloB, (long)row0 * ldc + col);
                    split_store(acc[mt][nt][1], ChiB, CloB, (long)row0 * ldc + col + 1);
                    split_store(acc[mt][nt][2], ChiB, CloB, (long)(row0 + 8) * ldc + col);
                    split_store(acc[mt][nt][3], ChiB, CloB, (long)(row0 + 8) * ldc + col + 1);
                }
            }
        }
    }
}

// ---------------- weight fp32 -> hi/lo bf16 split (vectorized x4) ----------
__global__ void convert_split_kernel(const float* __restrict__ src,
                                     bf16* __restrict__ hi, bf16* __restrict__ lo,
                                     int n4) {
    int i = blockIdx.x * 256 + threadIdx.x;
    if (i >= n4) return;
    float4 v = ((const float4*)src)[i];
    __nv_bfloat162 h0 = __floats2bfloat162_rn(v.x, v.y);
    __nv_bfloat162 h1 = __floats2bfloat162_rn(v.z, v.w);
    float2 f0 = __bfloat1622float2(h0);
    float2 f1 = __bfloat1622float2(h1);
    __nv_bfloat162 l0 = __floats2bfloat162_rn(v.x - f0.x, v.y - f0.y);
    __nv_bfloat162 l1 = __floats2bfloat162_rn(v.z - f1.x, v.w - f1.y);
    ((__nv_bfloat162*)hi)[i * 2]     = h0;
    ((__nv_bfloat162*)hi)[i * 2 + 1] = h1;
    ((__nv_bfloat162*)lo)[i * 2]     = l0;
    ((__nv_bfloat162*)lo)[i * 2 + 1] = l1;
}

// ---------------- rmsnorm ----------------
__device__ __forceinline__ float block_sum256(float v, float* sh) {
    #pragma unroll
    for (int o = 16; o; o >>= 1) v += __shfl_xor_sync(0xffffffffu, v, o);
    if ((threadIdx.x & 31) == 0) sh[threadIdx.x >> 5] = v;
    __syncthreads();
    float tot = 0.f;
    #pragma unroll
    for (int i = 0; i < 8; i++) tot += sh[i];
    return tot;
}

__global__ __launch_bounds__(256) void rms_motion_kernel(
    const float* __restrict__ x, const float* __restrict__ w)
{
    __shared__ float sh[8];
    int t = blockIdx.x, b = blockIdx.y, h = blockIdx.z;
    const float4* row = (const float4*)(x + ((long)b * LSEQ + h * TMOT + t) * DMODEL);
    const float4* wr  = (const float4*)(w + h * DMODEL);
    long obase = ((long)(h * 2 + b) * TMOT + t) * DMODEL + threadIdx.x * 4;
    float4 v = row[threadIdx.x];
    float tot = block_sum256(v.x*v.x + v.y*v.y + v.z*v.z + v.w*v.w, sh);
    float s = rsqrtf(tot * (1.f / DMODEL) + 1e-6f);
    float4 wv = wr[threadIdx.x];
    split_store(v.x * s * wv.x, g_xnh, g_xnl, obase + 0);
    split_store(v.y * s * wv.y, g_xnh, g_xnl, obase + 1);
    split_store(v.z * s * wv.z, g_xnh, g_xnl, obase + 2);
    split_store(v.w * s * wv.w, g_xnh, g_xnl, obase + 3);
}

__global__ __launch_bounds__(256) void rms_text_kernel(
    const float* __restrict__ x, const float* __restrict__ w)
{
    __shared__ float sh[8];
    int n = blockIdx.x, b = blockIdx.y, g = blockIdx.z;
    const float4* row = (const float4*)(x + ((long)b * LSEQ + 3 * TMOT + g * NTXT + n) * DMODEL);
    const float4* wr  = (const float4*)(w + g * DMODEL);
    long obase = ((long)(g * 2 + b) * NTXT + n) * DMODEL + threadIdx.x * 4;
    float4 v = row[threadIdx.x];
    float tot = block_sum256(v.x*v.x + v.y*v.y + v.z*v.z + v.w*v.w, sh);
    float s = rsqrtf(tot * (1.f / DMODEL) + 1e-6f);
    float4 wv = wr[threadIdx.x];
    split_store(v.x * s * wv.x, g_tnh, g_tnl, obase + 0);
    split_store(v.y * s * wv.y, g_tnh, g_tnl, obase + 1);
    split_store(v.z * s * wv.z, g_tnh, g_tnl, obase + 2);
    split_store(v.w * s * wv.w, g_tnh, g_tnl, obase + 3);
}

// ---------------- elementwise stages ----------------
__global__ void negA_kernel(const float* __restrict__ A_log) {
    int i = blockIdx.x * 256 + threadIdx.x;
    if (i < NHEAD * DIN * DSTATE) g_negA[i] = -expf(A_log[i]);
}

// depthwise causal conv (D_CONV=4) + bias + silu ; xi = first half of xz rows
__global__ void conv_silu_kernel(const float* __restrict__ cw, const float* __restrict__ cb) {
    int idx = blockIdx.x * 256 + threadIdx.x;
    if (idx >= NHEAD * 2 * TMOT * DIN) return;
    int d  = idx & (DIN - 1);
    int r  = idx >> 12;             // (h*2+b)*1024 + t
    int t  = r & (TMOT - 1);
    int hb = r >> 10;
    int h  = hb >> 1;
    const float* xi  = g_xz + (long)hb * TMOT * 8192 + d;    // row stride 2*din
    const float* cwd = cw + ((long)h * DIN + d) * 4;
    float acc = cb[h * DIN + d];
    #pragma unroll
    for (int k = 0; k < 4; k++) {
        int ti = t - 3 + k;
        if (ti >= 0) acc += xi[(long)ti * 8192] * cwd[k];
    }
    float v = acc / (1.f + __expf(-acc));
    g_xc[idx] = v;
    split_store(v, g_xch, g_xcl, idx);
}

__global__ void dt_act_kernel(const float* __restrict__ bias) {
    int idx = blockIdx.x * 256 + threadIdx.x;
    if (idx >= NHEAD * 2048 * DIN) return;
    int n = idx & (DIN - 1);
    int h = idx / (2048 * DIN);
    float v = g_dt[idx] + bias[h * DIN + n];
    g_dt[idx] = (v > 20.f) ? v : log1pf(__expf(v));
}

__global__ void silu_gate_kernel() {
    int idx = blockIdx.x * 256 + threadIdx.x;
    if (idx >= 5120 * HID) return;
    float g = g_gb[idx];
    float v = g / (1.f + __expf(-g)) * g_ub[idx];
    split_store(v, g_gbh, g_gbl, idx);
}

__global__ void scatter_motion_kernel(const float* __restrict__ x, float* __restrict__ out) {
    int idx = blockIdx.x * 256 + threadIdx.x;
    if (idx >= NHEAD * 2 * TMOT * DMODEL) return;
    int d  = idx & (DMODEL - 1);
    int r  = idx >> 10;
    int t  = r & (TMOT - 1);
    int hb = r >> 10;
    int h = hb >> 1, b = hb & 1;
    long o = ((long)b * LSEQ + h * TMOT + t) * DMODEL + d;
    out[o] = x[o] + g_mot[idx];
}

__global__ void scatter_text_kernel(const float* __restrict__ x, float* __restrict__ out) {
    int idx = blockIdx.x * 256 + threadIdx.x;
    if (idx >= NGRP * 2 * NTXT * DMODEL) return;
    int d  = idx & (DMODEL - 1);
    int r  = idx >> 10;
    int n  = r & (NTXT - 1);
    int gb = r >> 9;
    int g = gb >> 1, b = gb & 1;
    long o = ((long)b * LSEQ + 3 * TMOT + g * NTXT + n) * DMODEL + d;
    out[o] = x[o] + g_txt[idx];
}

// ---------------- selective scan: warp per (h,b,d), 4 states per lane ------
__global__ __launch_bounds__(256) void scan_kernel(const float* __restrict__ Dp) {
    int h = blockIdx.z, b = blockIdx.y;
    int warp = threadIdx.x >> 5, lane = threadIdx.x & 31;
    int d = blockIdx.x * 8 + warp;
    long hb = h * 2 + b;
    const float* dt_p = g_dt + hb * TMOT * (long)DIN + d;
    const float* u_p  = g_xc + hb * TMOT * (long)DIN + d;
    const float* bc_p = g_xdbl + hb * TMOT * (long)XDBLW;
    const float* z_p  = g_xz + hb * TMOT * 8192L + DIN + d;
    const float* A_p  = g_negA + ((long)h * DIN + d) * DSTATE + lane * 4;
    float a0 = A_p[0], a1 = A_p[1], a2 = A_p[2], a3 = A_p[3];
    float Dv = Dp[h * DIN + d];
    long ybase = hb * TMOT * (long)DIN + d;

    float h0 = 0.f, h1 = 0.f, h2 = 0.f, h3 = 0.f;
    for (int t = 0; t < TMOT; t++) {
        float dtv = __ldg(dt_p + (long)t * DIN);
        float uv  = __ldg(u_p  + (long)t * DIN);
        float4 Bv = *(const float4*)(bc_p + (long)t * XDBLW + DTRANK + lane * 4);
        float4 Cv = *(const float4*)(bc_p + (long)t * XDBLW + DTRANK + DSTATE + lane * 4);
        float du = dtv * uv;
        h0 = h0 * __expf(dtv * a0) + du * Bv.x;
        h1 = h1 * __expf(dtv * a1) + du * Bv.y;
        h2 = h2 * __expf(dtv * a2) + du * Bv.z;
        h3 = h3 * __expf(dtv * a3) + du * Bv.w;
        float p = h0 * Cv.x + h1 * Cv.y + h2 * Cv.z + h3 * Cv.w;
        p += __shfl_xor_sync(0xffffffffu, p, 16);
        p += __shfl_xor_sync(0xffffffffu, p, 8);
        p += __shfl_xor_sync(0xffffffffu, p, 4);
        p += __shfl_xor_sync(0xffffffffu, p, 2);
        p += __shfl_xor_sync(0xffffffffu, p, 1);
        if (lane == 0) {
            float y  = p + uv * Dv;
            float zv = __ldg(z_p + (long)t * 8192);
            float yo = y * zv / (1.f + __expf(-zv));
            split_store(yo, g_ymh, g_yml, ybase + (long)t * DIN);
        }
    }
}

// ---------------- host orchestration ----------------
static inline int cdiv(int a, int b) { return (a + b - 1) / b; }

extern "C" void kernel_launch(void* const* d_in, const int* in_sizes, int n_in,
                              void* d_out, int out_size)
{
    const float* x     = (const float*)d_in[0];
    const float* nmw   = (const float*)d_in[3];
    const float* ntw   = (const float*)d_in[4];
    const float* w_in  = (const float*)d_in[5];
    const float* cw    = (const float*)d_in[6];
    const float* cb    = (const float*)d_in[7];
    const float* w_x   = (const float*)d_in[8];
    const float* w_dt  = (const float*)d_in[9];
    const float* b_dt  = (const float*)d_in[10];
    const float* A_log = (const float*)d_in[11];
    const float* Dp    = (const float*)d_in[12];
    const float* w_out = (const float*)d_in[13];
    const float* wg    = (const float*)d_in[14];
    const float* wu    = (const float*)d_in[15];
    const float* wd    = (const float*)d_in[16];
    float* out = (float*)d_out;

    float *xz, *xc, *xdbl, *dtb, *mot, *gb, *ub, *txt;
    bf16 *xnh, *xnl, *xch, *xcl, *xdh, *xdl, *ymh, *yml, *tnh, *tnl, *gbh, *gbl;
    bf16 *wih, *wil, *wxh, *wxl, *wdth, *wdtl, *woh, *wol,
         *wgh, *wgl, *wuh, *wul, *wdh, *wdl;
    cudaGetSymbolAddress((void**)&xz,   g_xz);
    cudaGetSymbolAddress((void**)&xc,   g_xc);
    cudaGetSymbolAddress((void**)&xdbl, g_xdbl);
    cudaGetSymbolAddress((void**)&dtb,  g_dt);
    cudaGetSymbolAddress((void**)&mot,  g_mot);
    cudaGetSymbolAddress((void**)&gb,   g_gb);
    cudaGetSymbolAddress((void**)&ub,   g_ub);
    cudaGetSymbolAddress((void**)&txt,  g_txt);
    cudaGetSymbolAddress((void**)&xnh,  g_xnh);  cudaGetSymbolAddress((void**)&xnl, g_xnl);
    cudaGetSymbolAddress((void**)&xch,  g_xch);  cudaGetSymbolAddress((void**)&xcl, g_xcl);
    cudaGetSymbolAddress((void**)&xdh,  g_xdh);  cudaGetSymbolAddress((void**)&xdl, g_xdl);
    cudaGetSymbolAddress((void**)&ymh,  g_ymh);  cudaGetSymbolAddress((void**)&yml, g_yml);
    cudaGetSymbolAddress((void**)&tnh,  g_tnh);  cudaGetSymbolAddress((void**)&tnl, g_tnl);
    cudaGetSymbolAddress((void**)&gbh,  g_gbh);  cudaGetSymbolAddress((void**)&gbl, g_gbl);
    cudaGetSymbolAddress((void**)&wih,  g_wih);  cudaGetSymbolAddress((void**)&wil, g_wil);
    cudaGetSymbolAddress((void**)&wxh,  g_wxh);  cudaGetSymbolAddress((void**)&wxl, g_wxl);
    cudaGetSymbolAddress((void**)&wdth, g_wdth); cudaGetSymbolAddress((void**)&wdtl, g_wdtl);
    cudaGetSymbolAddress((void**)&woh,  g_woh);  cudaGetSymbolAddress((void**)&wol, g_wol);
    cudaGetSymbolAddress((void**)&wgh,  g_wgh);  cudaGetSymbolAddress((void**)&wgl, g_wgl);
    cudaGetSymbolAddress((void**)&wuh,  g_wuh);  cudaGetSymbolAddress((void**)&wul, g_wul);
    cudaGetSymbolAddress((void**)&wdh,  g_wdh);  cudaGetSymbolAddress((void**)&wdl, g_wdl);

    cudaFuncSetAttribute(gemm_mma,
                         cudaFuncAttributeMaxDynamicSharedMemorySize, GSMEM);

    // ---- weight splits (vectorized x4) ----
    {
        int n;
        n = NHEAD * 8192 * 1024 / 4;
        convert_split_kernel<<<cdiv(n, 256), 256>>>(w_in, wih, wil, n);
        n = NHEAD * 320 * 4096 / 4;
        convert_split_kernel<<<cdiv(n, 256), 256>>>(w_x, wxh, wxl, n);
        n = NHEAD * 4096 * 64 / 4;
        convert_split_kernel<<<cdiv(n, 256), 256>>>(w_dt, wdth, wdtl, n);
        n = NHEAD * 1024 * 4096 / 4;
        convert_split_kernel<<<cdiv(n, 256), 256>>>(w_out, woh, wol, n);
        n = 4096 * 1024 / 4;
        convert_split_kernel<<<cdiv(n, 256), 256>>>(wg, wgh, wgl, n);
        convert_split_kernel<<<cdiv(n, 256), 256>>>(wu, wuh, wul, n);
        convert_split_kernel<<<cdiv(n, 256), 256>>>(wd, wdh, wdl, n);
    }

    // ---- motion path ----
    negA_kernel<<<cdiv(NHEAD * DIN * DSTATE, 256), 256>>>(A_log);
    rms_motion_kernel<<<dim3(TMOT, BATCH, NHEAD), 256>>>(x, nmw);

    // in_proj: (2048x1024) @ (8192x1024)^T per head
    gemm_mma<<<dim3(8192 / GBN, 2048 / GBM, NHEAD), 256, GSMEM>>>(
        xnh, xnl, 1024, 2048L * 1024, wih, wil, 1024, 8192L * 1024,
        xz, 8192, 2048L * 8192, (bf16*)nullptr, (bf16*)nullptr, 0,
        2048, 8192, 1024);

    conv_silu_kernel<<<cdiv(NHEAD * 2 * TMOT * DIN, 256), 256>>>(cw, cb);

    // x_proj: (2048x4096) @ (320x4096)^T -> fp32 + hi/lo planes
    gemm_mma<<<dim3(3, 2048 / GBM, NHEAD), 256, GSMEM>>>(
        xch, xcl, DIN, 2048L * DIN, wxh, wxl, DIN, (long)XDBLW * DIN,
        xdbl, XDBLW, 2048L * XDBLW, xdh, xdl, 2048L * XDBLW,
        2048, XDBLW, DIN);

    // dt_proj: (2048x64) @ (4096x64)^T (A = first 64 cols of xdbl planes)
    gemm_mma<<<dim3(DIN / GBN, 2048 / GBM, NHEAD), 256, GSMEM>>>(
        xdh, xdl, XDBLW, 2048L * XDBLW, wdth, wdtl, DTRANK, (long)DIN * DTRANK,
        dtb, DIN, 2048L * DIN, (bf16*)nullptr, (bf16*)nullptr, 0,
        2048, DIN, DTRANK);

    dt_act_kernel<<<cdiv(NHEAD * 2048 * DIN, 256), 256>>>(b_dt);

    scan_kernel<<<dim3(DIN / 8, BATCH, NHEAD), 256>>>(Dp);

    // out_proj: (2048x4096) @ (1024x4096)^T
    gemm_mma<<<dim3(DMODEL / GBN, 2048 / GBM, NHEAD), 256, GSMEM>>>(
        ymh, yml, DIN, 2048L * DIN, woh, wol, DIN, (long)DMODEL * DIN,
        mot, DMODEL, 2048L * DMODEL, (bf16*)nullptr, (bf16*)nullptr, 0,
        2048, DMODEL, DIN);

    scatter_motion_kernel<<<cdiv(NHEAD * 2 * TMOT * DMODEL, 256), 256>>>(x, out);

    // ---- text path ----
    rms_text_kernel<<<dim3(NTXT, BATCH, NGRP), 256>>>(x, ntw);

    gemm_mma<<<dim3(HID / GBN, 5120 / GBM, 1), 256, GSMEM>>>(
        tnh, tnl, DMODEL, 0, wgh, wgl, DMODEL, 0,
        gb, HID, 0, (bf16*)nullptr, (bf16*)nullptr, 0,
        5120, HID, DMODEL);
    gemm_mma<<<dim3(HID / GBN, 5120 / GBM, 1), 256, GSMEM>>>(
        tnh, tnl, DMODEL, 0, wuh, wul, DMODEL, 0,
        ub, HID, 0, (bf16*)nullptr, (bf16*)nullptr, 0,
        5120, HID, DMODEL);

    silu_gate_kernel<<<cdiv(5120 * HID, 256), 256>>>();

    gemm_mma<<<dim3(DMODEL / GBN, 5120 / GBM, 1), 256, GSMEM>>>(
        gbh, gbl, HID, 0, wdh, wdl, HID, 0,
        txt, DMODEL, 0, (bf16*)nullptr, (bf16*)nullptr, 0,
        5120, DMODEL, HID);

    scatter_text_kernel<<<cdiv(NGRP * 2 * NTXT * DMODEL, 256), 256>>>(x, out);
}

// round 7
// speedup vs baseline: 1.1162x; 1.0449x over previous
#include <cuda_runtime.h>
#include <cuda_bf16.h>
#include <cstdint>
#include <cstddef>
#include <math.h>

// ---------------- problem constants (fixed by setup_inputs) ----------------
#define BATCH   2
#define TMOT    1024
#define DMODEL  1024
#define LSEQ    5632        // 3*TMOT + 5*NTXT
#define DIN     4096
#define DSTATE  128
#define DTRANK  64
#define HID     4096
#define NTXT    512
#define XDBLW   320         // dt_rank + 2*d_state
#define NHEAD   3
#define NGRP    5

// ---------------- scratch (static device globals; no allocation) -----------
__device__ float g_xn  [NHEAD*2048*1024];    // rmsnorm'd motion        (h,b,t,D)
__device__ float g_xz  [NHEAD*2048*8192];    // in_proj out (xi|z)      (h,b,t,2*din)
__device__ float g_xc  [NHEAD*2048*4096];    // conv+silu               (h,b,t,din)
__device__ float g_xdbl[NHEAD*2048*320];     // x_proj out (dt|B|C)
__device__ float g_dt  [NHEAD*2048*4096];    // softplus(dt)
__device__ float g_ym  [NHEAD*2048*4096];    // scan out, gated
__device__ float g_mot [NHEAD*2048*1024];    // out_proj result
__device__ float g_negA[NHEAD*4096*128];     // -exp(A_log)
__device__ float g_tn  [5120*1024];          // rmsnorm'd text (g,b,n,D)
__device__ float g_gb  [5120*4096];          // mlp gate  (then act in-place)
__device__ float g_ub  [5120*4096];          // mlp up
__device__ float g_txt [5120*1024];          // mlp down result

// ===================== warp-level bf16x3 tensor-core GEMM ===================
// C[M,N] = A[M,K] @ B[N,K]^T in ~fp32 precision via hi/lo bf16 split:
//   A = Ah + Al, B = Bh + Bl ;  D += Ah*Bh + Ah*Bl + Al*Bh
// Round-4 proven loader (fp32 + in-loop convert) and mainloop; tile shrunk to
// 128x64 so TWO CTAs co-reside per SM — one CTA's load/convert phase overlaps
// the other's HMMA phase (occupancy-2 fix for phase serialization).

#define GBM 128
#define GBN 64
#define GBK 32
#define ROWB    80                 // 32 bf16 (64B) + 16B pad
#define APLANE  (128 * ROWB)       // 10240 B
#define BPLANE  (64 * ROWB)        // 5120 B
#define STAGEB  (2 * APLANE + 2 * BPLANE)   // 30720 B: Ah, Al, Bh, Bl
#define GSMEM   (2 * STAGEB)       // 61440 B

__device__ __forceinline__ uint32_t smem_u32(const void* p) {
    return (uint32_t)__cvta_generic_to_shared(p);
}
__device__ __forceinline__ void ldsm4(uint32_t& r0, uint32_t& r1,
                                      uint32_t& r2, uint32_t& r3, uint32_t a) {
    asm volatile("ldmatrix.sync.aligned.m8n8.x4.shared.b16 {%0,%1,%2,%3}, [%4];"
                 : "=r"(r0), "=r"(r1), "=r"(r2), "=r"(r3) : "r"(a));
}
__device__ __forceinline__ void mma16816(float* c, uint32_t a0, uint32_t a1,
                                         uint32_t a2, uint32_t a3,
                                         uint32_t b0, uint32_t b1) {
    asm volatile(
        "mma.sync.aligned.m16n8k16.row.col.f32.bf16.bf16.f32 "
        "{%0,%1,%2,%3}, {%4,%5,%6,%7}, {%8,%9}, {%0,%1,%2,%3};"
        : "+f"(c[0]), "+f"(c[1]), "+f"(c[2]), "+f"(c[3])
        : "r"(a0), "r"(a1), "r"(a2), "r"(a3), "r"(b0), "r"(b1));
}
__device__ __forceinline__ void cvt_split(float4 v, uint2& hi, uint2& lo) {
    __nv_bfloat162 h0 = __floats2bfloat162_rn(v.x, v.y);
    __nv_bfloat162 h1 = __floats2bfloat162_rn(v.z, v.w);
    float2 f0 = __bfloat1622float2(h0);
    float2 f1 = __bfloat1622float2(h1);
    __nv_bfloat162 l0 = __floats2bfloat162_rn(v.x - f0.x, v.y - f0.y);
    __nv_bfloat162 l1 = __floats2bfloat162_rn(v.z - f1.x, v.w - f1.y);
    hi.x = *(uint32_t*)&h0;  hi.y = *(uint32_t*)&h1;
    lo.x = *(uint32_t*)&l0;  lo.y = *(uint32_t*)&l1;
}

__global__ __launch_bounds__(256, 2) void gemm_mma(
    const float* __restrict__ A, int lda, long sA,
    const float* __restrict__ Bw, int ldb, long sB,
    float* __restrict__ C, int ldc, long sC,
    int M, int N, int K)
{
    extern __shared__ char dsm[];
    A  += (long)blockIdx.z * sA;
    Bw += (long)blockIdx.z * sB;
    C  += (long)blockIdx.z * sC;

    const int tid  = threadIdx.x;
    const int wid  = tid >> 5;
    const int lane = tid & 31;
    const int bm = blockIdx.y * GBM;
    const int bn = blockIdx.x * GBN;
    const int wm = wid & 1;           // 0..1  (64-row groups)
    const int wn = wid >> 1;          // 0..3  (16-col groups)

    // ---- loader mapping ----
    // A: 128 rows x 2 halves (16 floats each) -> 256 slots
    const int rA  = tid >> 1;
    const int hfA = tid & 1;
    const float* Arow = A + (long)(bm + rA) * lda + hfA * 16;
    const uint32_t soffA = (uint32_t)(rA * ROWB + hfA * 32);
    // B: 64 rows x 4 quarters (8 floats each) -> 256 slots
    const int rB = tid >> 2;
    const int qB = tid & 3;
    const float* Brow = Bw + (long)(bn + rB) * ldb + qB * 8;
    const bool bok = (bn + rB) < N;
    const uint32_t soffB = (uint32_t)(rB * ROWB + qB * 16);

    float4 pa[4], pb[2];
    const int nch = K / GBK;

    auto fetch = [&](int c) {
        const int k0 = c * GBK;
        #pragma unroll
        for (int i = 0; i < 4; i++)
            pa[i] = *(const float4*)(Arow + k0 + i * 4);
        #pragma unroll
        for (int i = 0; i < 2; i++)
            pb[i] = bok ? *(const float4*)(Brow + k0 + i * 4)
                        : make_float4(0.f, 0.f, 0.f, 0.f);
    };
    auto store = [&](int st) {
        char* base = dsm + st * STAGEB;
        #pragma unroll
        for (int i = 0; i < 4; i++) {
            uint2 hi, lo;
            cvt_split(pa[i], hi, lo);
            *(uint2*)(base + soffA + i * 8) = hi;
            *(uint2*)(base + APLANE + soffA + i * 8) = lo;
        }
        #pragma unroll
        for (int i = 0; i < 2; i++) {
            uint2 hi, lo;
            cvt_split(pb[i], hi, lo);
            *(uint2*)(base + 2 * APLANE + soffB + i * 8) = hi;
            *(uint2*)(base + 2 * APLANE + BPLANE + soffB + i * 8) = lo;
        }
    };

    float acc[4][2][4];
    #pragma unroll
    for (int i = 0; i < 4; i++)
        #pragma unroll
        for (int j = 0; j < 2; j++)
            #pragma unroll
            for (int q = 0; q < 4; q++) acc[i][j][q] = 0.f;

    const uint32_t lmoff = (uint32_t)((lane & 15) * ROWB + (lane >> 4) * 16);
    const uint32_t sm0 = smem_u32(dsm);

    // ---- prologue ----
    fetch(0);
    store(0);
    if (nch > 1) fetch(1);
    __syncthreads();

    for (int c = 0; c < nch; c++) {
        const uint32_t sb = sm0 + (c & 1) * STAGEB;
        const uint32_t aH = sb + (uint32_t)(wm * 64 * ROWB) + lmoff;
        const uint32_t bH = sb + 2u * APLANE + (uint32_t)(wn * 16 * ROWB) + lmoff;
        #pragma unroll
        for (int ks = 0; ks < 2; ks++) {
            const uint32_t ko = ks * 32;   // 16 bf16 = 32 B
            uint32_t Ah[4][4], Al[4][4], Bh[2][2], Bl[2][2];
            #pragma unroll
            for (int mt = 0; mt < 4; mt++) {
                ldsm4(Ah[mt][0], Ah[mt][1], Ah[mt][2], Ah[mt][3],
                      aH + mt * 16 * ROWB + ko);
                ldsm4(Al[mt][0], Al[mt][1], Al[mt][2], Al[mt][3],
                      aH + APLANE + mt * 16 * ROWB + ko);
            }
            {
                uint32_t r0, r1, r2, r3;
                ldsm4(r0, r1, r2, r3, bH + ko);
                Bh[0][0] = r0; Bh[1][0] = r1; Bh[0][1] = r2; Bh[1][1] = r3;
                ldsm4(r0, r1, r2, r3, bH + BPLANE + ko);
                Bl[0][0] = r0; Bl[1][0] = r1; Bl[0][1] = r2; Bl[1][1] = r3;
            }
            #pragma unroll
            for (int mt = 0; mt < 4; mt++)
                #pragma unroll
                for (int nt = 0; nt < 2; nt++) {
                    mma16816(acc[mt][nt], Ah[mt][0], Ah[mt][1], Ah[mt][2],
                             Ah[mt][3], Bh[nt][0], Bh[nt][1]);
                    mma16816(acc[mt][nt], Ah[mt][0], Ah[mt][1], Ah[mt][2],
                             Ah[mt][3], Bl[nt][0], Bl[nt][1]);
                    mma16816(acc[mt][nt], Al[mt][0], Al[mt][1], Al[mt][2],
                             Al[mt][3], Bh[nt][0], Bh[nt][1]);
                }
        }
        if (c + 1 < nch) {
            store((c + 1) & 1);
            if (c + 2 < nch) fetch(c + 2);
        }
        __syncthreads();
    }

    // ---- epilogue ----
    #pragma unroll
    for (int mt = 0; mt < 4; mt++) {
        const int row0 = bm + wm * 64 + mt * 16 + (lane >> 2);
        #pragma unroll
        for (int nt = 0; nt < 2; nt++) {
            const int col = bn + wn * 16 + nt * 8 + (lane & 3) * 2;
            if (col < N) {
                *(float2*)(C + (long)row0 * ldc + col) =
                    make_float2(acc[mt][nt][0], acc[mt][nt][1]);
                *(float2*)(C + (long)(row0 + 8) * ldc + col) =
                    make_float2(acc[mt][nt][2], acc[mt][nt][3]);
            }
        }
    }
}

// ---------------- rmsnorm ----------------
__device__ __forceinline__ float block_sum256(float v, float* sh) {
    #pragma unroll
    for (int o = 16; o; o >>= 1) v += __shfl_xor_sync(0xffffffffu, v, o);
    if ((threadIdx.x & 31) == 0) sh[threadIdx.x >> 5] = v;
    __syncthreads();
    float tot = 0.f;
    #pragma unroll
    for (int i = 0; i < 8; i++) tot += sh[i];
    return tot;
}

__global__ __launch_bounds__(256) void rms_motion_kernel(
    const float* __restrict__ x, const float* __restrict__ w)
{
    __shared__ float sh[8];
    int t = blockIdx.x, b = blockIdx.y, h = blockIdx.z;
    const float4* row = (const float4*)(x + ((long)b * LSEQ + h * TMOT + t) * DMODEL);
    const float4* wr  = (const float4*)(w + h * DMODEL);
    float4* out = (float4*)(g_xn + ((long)(h * 2 + b) * TMOT + t) * DMODEL);
    float4 v = row[threadIdx.x];
    float tot = block_sum256(v.x*v.x + v.y*v.y + v.z*v.z + v.w*v.w, sh);
    float s = rsqrtf(tot * (1.f / DMODEL) + 1e-6f);
    float4 wv = wr[threadIdx.x];
    out[threadIdx.x] = make_float4(v.x*s*wv.x, v.y*s*wv.y, v.z*s*wv.z, v.w*s*wv.w);
}

__global__ __launch_bounds__(256) void rms_text_kernel(
    const float* __restrict__ x, const float* __restrict__ w)
{
    __shared__ float sh[8];
    int n = blockIdx.x, b = blockIdx.y, g = blockIdx.z;
    const float4* row = (const float4*)(x + ((long)b * LSEQ + 3 * TMOT + g * NTXT + n) * DMODEL);
    const float4* wr  = (const float4*)(w + g * DMODEL);
    float4* out = (float4*)(g_tn + ((long)(g * 2 + b) * NTXT + n) * DMODEL);
    float4 v = row[threadIdx.x];
    float tot = block_sum256(v.x*v.x + v.y*v.y + v.z*v.z + v.w*v.w, sh);
    float s = rsqrtf(tot * (1.f / DMODEL) + 1e-6f);
    float4 wv = wr[threadIdx.x];
    out[threadIdx.x] = make_float4(v.x*s*wv.x, v.y*s*wv.y, v.z*s*wv.z, v.w*s*wv.w);
}

// ---------------- elementwise stages ----------------
__global__ void negA_kernel(const float* __restrict__ A_log) {
    int i = blockIdx.x * 256 + threadIdx.x;
    if (i < NHEAD * DIN * DSTATE) g_negA[i] = -expf(A_log[i]);
}

// depthwise causal conv (D_CONV=4) + bias + silu ; xi = first half of xz rows
__global__ void conv_silu_kernel(const float* __restrict__ cw, const float* __restrict__ cb) {
    int idx = blockIdx.x * 256 + threadIdx.x;
    if (idx >= NHEAD * 2 * TMOT * DIN) return;
    int d  = idx & (DIN - 1);
    int r  = idx >> 12;             // (h*2+b)*1024 + t
    int t  = r & (TMOT - 1);
    int hb = r >> 10;
    int h  = hb >> 1;
    const float* xi  = g_xz + (long)hb * TMOT * 8192 + d;    // row stride 2*din
    const float* cwd = cw + ((long)h * DIN + d) * 4;
    float acc = cb[h * DIN + d];
    #pragma unroll
    for (int k = 0; k < 4; k++) {
        int ti = t - 3 + k;
        if (ti >= 0) acc += xi[(long)ti * 8192] * cwd[k];
    }
    g_xc[idx] = acc / (1.f + __expf(-acc));
}

__global__ void dt_act_kernel(const float* __restrict__ bias) {
    int idx = blockIdx.x * 256 + threadIdx.x;
    if (idx >= NHEAD * 2048 * DIN) return;
    int n = idx & (DIN - 1);
    int h = idx / (2048 * DIN);
    float v = g_dt[idx] + bias[h * DIN + n];
    g_dt[idx] = (v > 20.f) ? v : log1pf(__expf(v));
}

__global__ void silu_gate_kernel() {
    int idx = blockIdx.x * 256 + threadIdx.x;
    if (idx >= 5120 * HID) return;
    float g = g_gb[idx];
    g_gb[idx] = g / (1.f + __expf(-g)) * g_ub[idx];
}

__global__ void scatter_motion_kernel(const float* __restrict__ x, float* __restrict__ out) {
    int idx = blockIdx.x * 256 + threadIdx.x;
    if (idx >= NHEAD * 2 * TMOT * DMODEL) return;
    int d  = idx & (DMODEL - 1);
    int r  = idx >> 10;
    int t  = r & (TMOT - 1);
    int hb = r >> 10;
    int h = hb >> 1, b = hb & 1;
    long o = ((long)b * LSEQ + h * TMOT + t) * DMODEL + d;
    out[o] = x[o] + g_mot[idx];
}

__global__ void scatter_text_kernel(const float* __restrict__ x, float* __restrict__ out) {
    int idx = blockIdx.x * 256 + threadIdx.x;
    if (idx >= NGRP * 2 * NTXT * DMODEL) return;
    int d  = idx & (DMODEL - 1);
    int r  = idx >> 10;
    int n  = r & (NTXT - 1);
    int gb = r >> 9;
    int g = gb >> 1, b = gb & 1;
    long o = ((long)b * LSEQ + 3 * TMOT + g * NTXT + n) * DMODEL + d;
    out[o] = x[o] + g_txt[idx];
}

// ---------------- selective scan: warp per (h,b,d), 4 states per lane ------
__global__ __launch_bounds__(256) void scan_kernel(const float* __restrict__ Dp) {
    int h = blockIdx.z, b = blockIdx.y;
    int warp = threadIdx.x >> 5, lane = threadIdx.x & 31;
    int d = blockIdx.x * 8 + warp;
    long hb = h * 2 + b;
    const float* dt_p = g_dt + hb * TMOT * (long)DIN + d;
    const float* u_p  = g_xc + hb * TMOT * (long)DIN + d;
    const float* bc_p = g_xdbl + hb * TMOT * (long)XDBLW;
    const float* z_p  = g_xz + hb * TMOT * 8192L + DIN + d;
    const float* A_p  = g_negA + ((long)h * DIN + d) * DSTATE + lane * 4;
    float a0 = A_p[0], a1 = A_p[1], a2 = A_p[2], a3 = A_p[3];
    float Dv = Dp[h * DIN + d];
    float* y_p = g_ym + hb * TMOT * (long)DIN + d;

    float h0 = 0.f, h1 = 0.f, h2 = 0.f, h3 = 0.f;
    for (int t = 0; t < TMOT; t++) {
        float dtv = __ldg(dt_p + (long)t * DIN);
        float uv  = __ldg(u_p  + (long)t * DIN);
        float4 Bv = *(const float4*)(bc_p + (long)t * XDBLW + DTRANK + lane * 4);
        float4 Cv = *(const float4*)(bc_p + (long)t * XDBLW + DTRANK + DSTATE + lane * 4);
        float du = dtv * uv;
        h0 = h0 * __expf(dtv * a0) + du * Bv.x;
        h1 = h1 * __expf(dtv * a1) + du * Bv.y;
        h2 = h2 * __expf(dtv * a2) + du * Bv.z;
        h3 = h3 * __expf(dtv * a3) + du * Bv.w;
        float p = h0 * Cv.x + h1 * Cv.y + h2 * Cv.z + h3 * Cv.w;
        p += __shfl_xor_sync(0xffffffffu, p, 16);
        p += __shfl_xor_sync(0xffffffffu, p, 8);
        p += __shfl_xor_sync(0xffffffffu, p, 4);
        p += __shfl_xor_sync(0xffffffffu, p, 2);
        p += __shfl_xor_sync(0xffffffffu, p, 1);
        if (lane == 0) {
            float y  = p + uv * Dv;
            float zv = __ldg(z_p + (long)t * 8192);
            y_p[(long)t * DIN] = y * zv / (1.f + __expf(-zv));
        }
    }
}

// ---------------- host orchestration ----------------
static inline int cdiv(int a, int b) { return (a + b - 1) / b; }

extern "C" void kernel_launch(void* const* d_in, const int* in_sizes, int n_in,
                              void* d_out, int out_size)
{
    const float* x     = (const float*)d_in[0];
    const float* nmw   = (const float*)d_in[3];
    const float* ntw   = (const float*)d_in[4];
    const float* w_in  = (const float*)d_in[5];
    const float* cw    = (const float*)d_in[6];
    const float* cb    = (const float*)d_in[7];
    const float* w_x   = (const float*)d_in[8];
    const float* w_dt  = (const float*)d_in[9];
    const float* b_dt  = (const float*)d_in[10];
    const float* A_log = (const float*)d_in[11];
    const float* Dp    = (const float*)d_in[12];
    const float* w_out = (const float*)d_in[13];
    const float* wg    = (const float*)d_in[14];
    const float* wu    = (const float*)d_in[15];
    const float* wd    = (const float*)d_in[16];
    float* out = (float*)d_out;

    float *xn, *xz, *xc, *xdbl, *dtb, *ym, *mot, *tn, *gb, *ub, *txt;
    cudaGetSymbolAddress((void**)&xn,   g_xn);
    cudaGetSymbolAddress((void**)&xz,   g_xz);
    cudaGetSymbolAddress((void**)&xc,   g_xc);
    cudaGetSymbolAddress((void**)&xdbl, g_xdbl);
    cudaGetSymbolAddress((void**)&dtb,  g_dt);
    cudaGetSymbolAddress((void**)&ym,   g_ym);
    cudaGetSymbolAddress((void**)&mot,  g_mot);
    cudaGetSymbolAddress((void**)&tn,   g_tn);
    cudaGetSymbolAddress((void**)&gb,   g_gb);
    cudaGetSymbolAddress((void**)&ub,   g_ub);
    cudaGetSymbolAddress((void**)&txt,  g_txt);

    cudaFuncSetAttribute(gemm_mma,
                         cudaFuncAttributeMaxDynamicSharedMemorySize, GSMEM);

    // ---- motion path ----
    negA_kernel<<<cdiv(NHEAD * DIN * DSTATE, 256), 256>>>(A_log);
    rms_motion_kernel<<<dim3(TMOT, BATCH, NHEAD), 256>>>(x, nmw);

    // in_proj: (2048x1024) @ (8192x1024)^T per head
    gemm_mma<<<dim3(8192 / GBN, 2048 / GBM, NHEAD), 256, GSMEM>>>(
        xn, 1024, 2048L * 1024, w_in, 1024, 8192L * 1024,
        xz, 8192, 2048L * 8192, 2048, 8192, 1024);

    conv_silu_kernel<<<cdiv(NHEAD * 2 * TMOT * DIN, 256), 256>>>(cw, cb);

    // x_proj: (2048x4096) @ (320x4096)^T   (320 = 5 * 64 exactly)
    gemm_mma<<<dim3(XDBLW / GBN, 2048 / GBM, NHEAD), 256, GSMEM>>>(
        xc, DIN, 2048L * DIN, w_x, DIN, (long)XDBLW * DIN,
        xdbl, XDBLW, 2048L * XDBLW, 2048, XDBLW, DIN);

    // dt_proj: (2048x64) @ (4096x64)^T (A = first 64 cols of xdbl)
    gemm_mma<<<dim3(DIN / GBN, 2048 / GBM, NHEAD), 256, GSMEM>>>(
        xdbl, XDBLW, 2048L * XDBLW, w_dt, DTRANK, (long)DIN * DTRANK,
        dtb, DIN, 2048L * DIN, 2048, DIN, DTRANK);

    dt_act_kernel<<<cdiv(NHEAD * 2048 * DIN, 256), 256>>>(b_dt);

    scan_kernel<<<dim3(DIN / 8, BATCH, NHEAD), 256>>>(Dp);

    // out_proj: (2048x4096) @ (1024x4096)^T
    gemm_mma<<<dim3(DMODEL / GBN, 2048 / GBM, NHEAD), 256, GSMEM>>>(
        ym, DIN, 2048L * DIN, w_out, DIN, (long)DMODEL * DIN,
        mot, DMODEL, 2048L * DMODEL, 2048, DMODEL, DIN);

    scatter_motion_kernel<<<cdiv(NHEAD * 2 * TMOT * DMODEL, 256), 256>>>(x, out);

    // ---- text path ----
    rms_text_kernel<<<dim3(NTXT, BATCH, NGRP), 256>>>(x, ntw);

    gemm_mma<<<dim3(HID / GBN, 5120 / GBM, 1), 256, GSMEM>>>(
        tn, DMODEL, 0, wg, DMODEL, 0, gb, HID, 0, 5120, HID, DMODEL);
    gemm_mma<<<dim3(HID / GBN, 5120 / GBM, 1), 256, GSMEM>>>(
        tn, DMODEL, 0, wu, DMODEL, 0, ub, HID, 0, 5120, HID, DMODEL);

    silu_gate_kernel<<<cdiv(5120 * HID, 256), 256>>>();

    gemm_mma<<<dim3(DMODEL / GBN, 5120 / GBM, 1), 256, GSMEM>>>(
        gb, HID, 0, wd, HID, 0, txt, DMODEL, 0, 5120, DMODEL, HID);

    scatter_text_kernel<<<cdiv(NGRP * 2 * NTXT * DMODEL, 256), 256>>>(x, out);
}

// round 8
// speedup vs baseline: 1.3127x; 1.1761x over previous
#include <cuda_runtime.h>
#include <cuda_bf16.h>
#include <cuda_fp16.h>
#include <cstdint>
#include <cstddef>
#include <math.h>

// ---------------- problem constants (fixed by setup_inputs) ----------------
#define BATCH   2
#define TMOT    1024
#define DMODEL  1024
#define LSEQ    5632        // 3*TMOT + 5*NTXT
#define DIN     4096
#define DSTATE  128
#define DTRANK  64
#define HID     4096
#define NTXT    512
#define XDBLW   320         // dt_rank + 2*d_state
#define NHEAD   3
#define NGRP    5

// ---------------- scratch (static device globals; no allocation) -----------
__device__ float g_xn  [NHEAD*2048*1024];    // rmsnorm'd motion        (h,b,t,D)
__device__ float g_xz  [NHEAD*2048*8192];    // in_proj out (xi|z)      (h,b,t,2*din)
__device__ float g_xc  [NHEAD*2048*4096];    // conv+silu               (h,b,t,din)
__device__ float g_xdbl[NHEAD*2048*320];     // x_proj out (dt|B|C)
__device__ float g_dt  [NHEAD*2048*4096];    // softplus(dt)
__device__ float g_ym  [NHEAD*2048*4096];    // scan out, gated
__device__ float g_mot [NHEAD*2048*1024];    // out_proj result
__device__ float g_negA[NHEAD*4096*128];     // -exp(A_log)
__device__ float g_tn  [5120*1024];          // rmsnorm'd text (g,b,n,D)
__device__ float g_gb  [5120*4096];          // mlp gate  (then act in-place)
__device__ float g_ub  [5120*4096];          // mlp up
__device__ float g_txt [5120*1024];          // mlp down result

// ===================== warp-level fp16 2-term tensor-core GEMM ==============
// C[M,N] = A[M,K] @ B[N,K]^T ;  A rounded to fp16 (Ah), B split Bh + Bl:
//   D = Ah*Bh + Ah*Bl        (error ~ (A-Ah)*B ~ 2^-11 rel, ~2e-4 RMS)
// Round-4 proven structure (fp32 gmem loads + in-loop convert, reg-prefetch
// double-buffered smem, 128x128 CTA tile, 8 warps 64x32 each); MMA count 2/3.

#define GBM 128
#define GBN 128
#define GBK 32
#define ROWB    80                 // 32 fp16 (64B) + 16B pad
#define APLANE  (128 * ROWB)       // 10240 B
#define STAGEB  (3 * APLANE)       // A, Bh, Bl = 30720 B
#define GSMEM   (2 * STAGEB)       // 61440 B

__device__ __forceinline__ uint32_t smem_u32(const void* p) {
    return (uint32_t)__cvta_generic_to_shared(p);
}
__device__ __forceinline__ void ldsm4(uint32_t& r0, uint32_t& r1,
                                      uint32_t& r2, uint32_t& r3, uint32_t a) {
    asm volatile("ldmatrix.sync.aligned.m8n8.x4.shared.b16 {%0,%1,%2,%3}, [%4];"
                 : "=r"(r0), "=r"(r1), "=r"(r2), "=r"(r3) : "r"(a));
}
__device__ __forceinline__ void mma16816(float* c, uint32_t a0, uint32_t a1,
                                         uint32_t a2, uint32_t a3,
                                         uint32_t b0, uint32_t b1) {
    asm volatile(
        "mma.sync.aligned.m16n8k16.row.col.f32.f16.f16.f32 "
        "{%0,%1,%2,%3}, {%4,%5,%6,%7}, {%8,%9}, {%0,%1,%2,%3};"
        : "+f"(c[0]), "+f"(c[1]), "+f"(c[2]), "+f"(c[3])
        : "r"(a0), "r"(a1), "r"(a2), "r"(a3), "r"(b0), "r"(b1));
}
__device__ __forceinline__ void cvt_f16(float4 v, uint2& hi) {
    __half2 h0 = __floats2half2_rn(v.x, v.y);
    __half2 h1 = __floats2half2_rn(v.z, v.w);
    hi.x = *(uint32_t*)&h0;  hi.y = *(uint32_t*)&h1;
}
__device__ __forceinline__ void cvt_split_f16(float4 v, uint2& hi, uint2& lo) {
    __half2 h0 = __floats2half2_rn(v.x, v.y);
    __half2 h1 = __floats2half2_rn(v.z, v.w);
    float2 f0 = __half22float2(h0);
    float2 f1 = __half22float2(h1);
    __half2 l0 = __floats2half2_rn(v.x - f0.x, v.y - f0.y);
    __half2 l1 = __floats2half2_rn(v.z - f1.x, v.w - f1.y);
    hi.x = *(uint32_t*)&h0;  hi.y = *(uint32_t*)&h1;
    lo.x = *(uint32_t*)&l0;  lo.y = *(uint32_t*)&l1;
}

__global__ __launch_bounds__(256, 1) void gemm_mma(
    const float* __restrict__ A, int lda, long sA,
    const float* __restrict__ Bw, int ldb, long sB,
    float* __restrict__ C, int ldc, long sC,
    int M, int N, int K)
{
    extern __shared__ char dsm[];
    A  += (long)blockIdx.z * sA;
    Bw += (long)blockIdx.z * sB;
    C  += (long)blockIdx.z * sC;

    const int tid  = threadIdx.x;
    const int wid  = tid >> 5;
    const int lane = tid & 31;
    const int bm = blockIdx.y * GBM;
    const int bn = blockIdx.x * GBN;
    const int wm = wid >> 2;          // 0..1
    const int wn = wid & 3;           // 0..3

    // ---- loader mapping: thread -> (row, 16-col half) ----
    const int r  = tid >> 1;
    const int hf = tid & 1;
    const float* Arow = A  + (long)(bm + r) * lda + hf * 16;
    const float* Brow = Bw + (long)(bn + r) * ldb + hf * 16;
    const bool bok = (bn + r) < N;
    const uint32_t soff = (uint32_t)(r * ROWB + hf * 32);

    float4 pa[4], pb[4];
    const int nch = K / GBK;

    auto fetch = [&](int c) {
        const int k0 = c * GBK;
        #pragma unroll
        for (int i = 0; i < 4; i++) {
            pa[i] = *(const float4*)(Arow + k0 + i * 4);
            pb[i] = bok ? *(const float4*)(Brow + k0 + i * 4)
                        : make_float4(0.f, 0.f, 0.f, 0.f);
        }
    };
    auto store = [&](int st) {
        char* base = dsm + st * STAGEB;
        #pragma unroll
        for (int i = 0; i < 4; i++) {
            uint2 ah;
            cvt_f16(pa[i], ah);
            *(uint2*)(base + soff + i * 8) = ah;
            uint2 hi, lo;
            cvt_split_f16(pb[i], hi, lo);
            *(uint2*)(base + 1 * APLANE + soff + i * 8) = hi;
            *(uint2*)(base + 2 * APLANE + soff + i * 8) = lo;
        }
    };

    float acc[4][4][4];
    #pragma unroll
    for (int i = 0; i < 4; i++)
        #pragma unroll
        for (int j = 0; j < 4; j++)
            #pragma unroll
            for (int q = 0; q < 4; q++) acc[i][j][q] = 0.f;

    // ldmatrix per-lane offset: rows lane%16, 16B half lane/16
    const uint32_t lmoff = (uint32_t)((lane & 15) * ROWB + (lane >> 4) * 16);
    const uint32_t sm0 = smem_u32(dsm);

    // ---- prologue ----
    fetch(0);
    store(0);
    if (nch > 1) fetch(1);
    __syncthreads();

    for (int c = 0; c < nch; c++) {
        const uint32_t sb = sm0 + (c & 1) * STAGEB;
        const uint32_t aH = sb + (uint32_t)(wm * 64 * ROWB) + lmoff;
        const uint32_t bH = sb + 1u * APLANE + (uint32_t)(wn * 32 * ROWB) + lmoff;
        #pragma unroll
        for (int ks = 0; ks < 2; ks++) {
            const uint32_t ko = ks * 32;   // 16 fp16 = 32 B
            uint32_t Ah[4][4], Bh[4][2], Bl[4][2];
            #pragma unroll
            for (int mt = 0; mt < 4; mt++)
                ldsm4(Ah[mt][0], Ah[mt][1], Ah[mt][2], Ah[mt][3],
                      aH + mt * 16 * ROWB + ko);
            #pragma unroll
            for (int p = 0; p < 2; p++) {
                uint32_t r0, r1, r2, r3;
                ldsm4(r0, r1, r2, r3, bH + p * 16 * ROWB + ko);
                Bh[2*p][0] = r0; Bh[2*p+1][0] = r1;
                Bh[2*p][1] = r2; Bh[2*p+1][1] = r3;
                ldsm4(r0, r1, r2, r3, bH + APLANE + p * 16 * ROWB + ko);
                Bl[2*p][0] = r0; Bl[2*p+1][0] = r1;
                Bl[2*p][1] = r2; Bl[2*p+1][1] = r3;
            }
            #pragma unroll
            for (int mt = 0; mt < 4; mt++)
                #pragma unroll
                for (int nt = 0; nt < 4; nt++) {
                    mma16816(acc[mt][nt], Ah[mt][0], Ah[mt][1], Ah[mt][2],
                             Ah[mt][3], Bh[nt][0], Bh[nt][1]);
                    mma16816(acc[mt][nt], Ah[mt][0], Ah[mt][1], Ah[mt][2],
                             Ah[mt][3], Bl[nt][0], Bl[nt][1]);
                }
        }
        if (c + 1 < nch) {
            store((c + 1) & 1);
            if (c + 2 < nch) fetch(c + 2);
        }
        __syncthreads();
    }

    // ---- epilogue ----
    #pragma unroll
    for (int mt = 0; mt < 4; mt++) {
        const int row0 = bm + wm * 64 + mt * 16 + (lane >> 2);
        #pragma unroll
        for (int nt = 0; nt < 4; nt++) {
            const int col = bn + wn * 32 + nt * 8 + (lane & 3) * 2;
            if (col < N) {
                *(float2*)(C + (long)row0 * ldc + col) =
                    make_float2(acc[mt][nt][0], acc[mt][nt][1]);
                *(float2*)(C + (long)(row0 + 8) * ldc + col) =
                    make_float2(acc[mt][nt][2], acc[mt][nt][3]);
            }
        }
    }
}

// ---------------- rmsnorm ----------------
__device__ __forceinline__ float block_sum256(float v, float* sh) {
    #pragma unroll
    for (int o = 16; o; o >>= 1) v += __shfl_xor_sync(0xffffffffu, v, o);
    if ((threadIdx.x & 31) == 0) sh[threadIdx.x >> 5] = v;
    __syncthreads();
    float tot = 0.f;
    #pragma unroll
    for (int i = 0; i < 8; i++) tot += sh[i];
    return tot;
}

__global__ __launch_bounds__(256) void rms_motion_kernel(
    const float* __restrict__ x, const float* __restrict__ w)
{
    __shared__ float sh[8];
    int t = blockIdx.x, b = blockIdx.y, h = blockIdx.z;
    const float4* row = (const float4*)(x + ((long)b * LSEQ + h * TMOT + t) * DMODEL);
    const float4* wr  = (const float4*)(w + h * DMODEL);
    float4* out = (float4*)(g_xn + ((long)(h * 2 + b) * TMOT + t) * DMODEL);
    float4 v = row[threadIdx.x];
    float tot = block_sum256(v.x*v.x + v.y*v.y + v.z*v.z + v.w*v.w, sh);
    float s = rsqrtf(tot * (1.f / DMODEL) + 1e-6f);
    float4 wv = wr[threadIdx.x];
    out[threadIdx.x] = make_float4(v.x*s*wv.x, v.y*s*wv.y, v.z*s*wv.z, v.w*s*wv.w);
}

__global__ __launch_bounds__(256) void rms_text_kernel(
    const float* __restrict__ x, const float* __restrict__ w)
{
    __shared__ float sh[8];
    int n = blockIdx.x, b = blockIdx.y, g = blockIdx.z;
    const float4* row = (const float4*)(x + ((long)b * LSEQ + 3 * TMOT + g * NTXT + n) * DMODEL);
    const float4* wr  = (const float4*)(w + g * DMODEL);
    float4* out = (float4*)(g_tn + ((long)(g * 2 + b) * NTXT + n) * DMODEL);
    float4 v = row[threadIdx.x];
    float tot = block_sum256(v.x*v.x + v.y*v.y + v.z*v.z + v.w*v.w, sh);
    float s = rsqrtf(tot * (1.f / DMODEL) + 1e-6f);
    float4 wv = wr[threadIdx.x];
    out[threadIdx.x] = make_float4(v.x*s*wv.x, v.y*s*wv.y, v.z*s*wv.z, v.w*s*wv.w);
}

// ---------------- elementwise stages ----------------
__global__ void negA_kernel(const float* __restrict__ A_log) {
    int i = blockIdx.x * 256 + threadIdx.x;
    if (i < NHEAD * DIN * DSTATE) g_negA[i] = -expf(A_log[i]);
}

// depthwise causal conv (D_CONV=4) + bias + silu ; xi = first half of xz rows
__global__ void conv_silu_kernel(const float* __restrict__ cw, const float* __restrict__ cb) {
    int idx = blockIdx.x * 256 + threadIdx.x;
    if (idx >= NHEAD * 2 * TMOT * DIN) return;
    int d  = idx & (DIN - 1);
    int r  = idx >> 12;             // (h*2+b)*1024 + t
    int t  = r & (TMOT - 1);
    int hb = r >> 10;
    int h  = hb >> 1;
    const float* xi  = g_xz + (long)hb * TMOT * 8192 + d;    // row stride 2*din
    const float* cwd = cw + ((long)h * DIN + d) * 4;
    float acc = cb[h * DIN + d];
    #pragma unroll
    for (int k = 0; k < 4; k++) {
        int ti = t - 3 + k;
        if (ti >= 0) acc += xi[(long)ti * 8192] * cwd[k];
    }
    g_xc[idx] = acc / (1.f + __expf(-acc));
}

__global__ void dt_act_kernel(const float* __restrict__ bias) {
    int idx = blockIdx.x * 256 + threadIdx.x;
    if (idx >= NHEAD * 2048 * DIN) return;
    int n = idx & (DIN - 1);
    int h = idx / (2048 * DIN);
    float v = g_dt[idx] + bias[h * DIN + n];
    g_dt[idx] = (v > 20.f) ? v : log1pf(__expf(v));
}

__global__ void silu_gate_kernel() {
    int idx = blockIdx.x * 256 + threadIdx.x;
    if (idx >= 5120 * HID) return;
    float g = g_gb[idx];
    g_gb[idx] = g / (1.f + __expf(-g)) * g_ub[idx];
}

__global__ void scatter_motion_kernel(const float* __restrict__ x, float* __restrict__ out) {
    int idx = blockIdx.x * 256 + threadIdx.x;
    if (idx >= NHEAD * 2 * TMOT * DMODEL) return;
    int d  = idx & (DMODEL - 1);
    int r  = idx >> 10;
    int t  = r & (TMOT - 1);
    int hb = r >> 10;
    int h = hb >> 1, b = hb & 1;
    long o = ((long)b * LSEQ + h * TMOT + t) * DMODEL + d;
    out[o] = x[o] + g_mot[idx];
}

__global__ void scatter_text_kernel(const float* __restrict__ x, float* __restrict__ out) {
    int idx = blockIdx.x * 256 + threadIdx.x;
    if (idx >= NGRP * 2 * NTXT * DMODEL) return;
    int d  = idx & (DMODEL - 1);
    int r  = idx >> 10;
    int n  = r & (NTXT - 1);
    int gb = r >> 9;
    int g = gb >> 1, b = gb & 1;
    long o = ((long)b * LSEQ + 3 * TMOT + g * NTXT + n) * DMODEL + d;
    out[o] = x[o] + g_txt[idx];
}

// ---------------- selective scan: warp per (h,b,d), 4 states per lane ------
__global__ __launch_bounds__(256) void scan_kernel(const float* __restrict__ Dp) {
    int h = blockIdx.z, b = blockIdx.y;
    int warp = threadIdx.x >> 5, lane = threadIdx.x & 31;
    int d = blockIdx.x * 8 + warp;
    long hb = h * 2 + b;
    const float* dt_p = g_dt + hb * TMOT * (long)DIN + d;
    const float* u_p  = g_xc + hb * TMOT * (long)DIN + d;
    const float* bc_p = g_xdbl + hb * TMOT * (long)XDBLW;
    const float* z_p  = g_xz + hb * TMOT * 8192L + DIN + d;
    const float* A_p  = g_negA + ((long)h * DIN + d) * DSTATE + lane * 4;
    float a0 = A_p[0], a1 = A_p[1], a2 = A_p[2], a3 = A_p[3];
    float Dv = Dp[h * DIN + d];
    float* y_p = g_ym + hb * TMOT * (long)DIN + d;

    float h0 = 0.f, h1 = 0.f, h2 = 0.f, h3 = 0.f;
    for (int t = 0; t < TMOT; t++) {
        float dtv = __ldg(dt_p + (long)t * DIN);
        float uv  = __ldg(u_p  + (long)t * DIN);
        float4 Bv = *(const float4*)(bc_p + (long)t * XDBLW + DTRANK + lane * 4);
        float4 Cv = *(const float4*)(bc_p + (long)t * XDBLW + DTRANK + DSTATE + lane * 4);
        float du = dtv * uv;
        h0 = h0 * __expf(dtv * a0) + du * Bv.x;
        h1 = h1 * __expf(dtv * a1) + du * Bv.y;
        h2 = h2 * __expf(dtv * a2) + du * Bv.z;
        h3 = h3 * __expf(dtv * a3) + du * Bv.w;
        float p = h0 * Cv.x + h1 * Cv.y + h2 * Cv.z + h3 * Cv.w;
        p += __shfl_xor_sync(0xffffffffu, p, 16);
        p += __shfl_xor_sync(0xffffffffu, p, 8);
        p += __shfl_xor_sync(0xffffffffu, p, 4);
        p += __shfl_xor_sync(0xffffffffu, p, 2);
        p += __shfl_xor_sync(0xffffffffu, p, 1);
        if (lane == 0) {
            float y  = p + uv * Dv;
            float zv = __ldg(z_p + (long)t * 8192);
            y_p[(long)t * DIN] = y * zv / (1.f + __expf(-zv));
        }
    }
}

// ---------------- host orchestration ----------------
static inline int cdiv(int a, int b) { return (a + b - 1) / b; }

extern "C" void kernel_launch(void* const* d_in, const int* in_sizes, int n_in,
                              void* d_out, int out_size)
{
    const float* x     = (const float*)d_in[0];
    const float* nmw   = (const float*)d_in[3];
    const float* ntw   = (const float*)d_in[4];
    const float* w_in  = (const float*)d_in[5];
    const float* cw    = (const float*)d_in[6];
    const float* cb    = (const float*)d_in[7];
    const float* w_x   = (const float*)d_in[8];
    const float* w_dt  = (const float*)d_in[9];
    const float* b_dt  = (const float*)d_in[10];
    const float* A_log = (const float*)d_in[11];
    const float* Dp    = (const float*)d_in[12];
    const float* w_out = (const float*)d_in[13];
    const float* wg    = (const float*)d_in[14];
    const float* wu    = (const float*)d_in[15];
    const float* wd    = (const float*)d_in[16];
    float* out = (float*)d_out;

    float *xn, *xz, *xc, *xdbl, *dtb, *ym, *mot, *tn, *gb, *ub, *txt;
    cudaGetSymbolAddress((void**)&xn,   g_xn);
    cudaGetSymbolAddress((void**)&xz,   g_xz);
    cudaGetSymbolAddress((void**)&xc,   g_xc);
    cudaGetSymbolAddress((void**)&xdbl, g_xdbl);
    cudaGetSymbolAddress((void**)&dtb,  g_dt);
    cudaGetSymbolAddress((void**)&ym,   g_ym);
    cudaGetSymbolAddress((void**)&mot,  g_mot);
    cudaGetSymbolAddress((void**)&tn,   g_tn);
    cudaGetSymbolAddress((void**)&gb,   g_gb);
    cudaGetSymbolAddress((void**)&ub,   g_ub);
    cudaGetSymbolAddress((void**)&txt,  g_txt);

    cudaFuncSetAttribute(gemm_mma,
                         cudaFuncAttributeMaxDynamicSharedMemorySize, GSMEM);

    // ---- motion path ----
    negA_kernel<<<cdiv(NHEAD * DIN * DSTATE, 256), 256>>>(A_log);
    rms_motion_kernel<<<dim3(TMOT, BATCH, NHEAD), 256>>>(x, nmw);

    // in_proj: (2048x1024) @ (8192x1024)^T per head
    gemm_mma<<<dim3(8192 / GBN, 2048 / GBM, NHEAD), 256, GSMEM>>>(
        xn, 1024, 2048L * 1024, w_in, 1024, 8192L * 1024,
        xz, 8192, 2048L * 8192, 2048, 8192, 1024);

    conv_silu_kernel<<<cdiv(NHEAD * 2 * TMOT * DIN, 256), 256>>>(cw, cb);

    // x_proj: (2048x4096) @ (320x4096)^T
    gemm_mma<<<dim3(cdiv(XDBLW, GBN), 2048 / GBM, NHEAD), 256, GSMEM>>>(
        xc, DIN, 2048L * DIN, w_x, DIN, (long)XDBLW * DIN,
        xdbl, XDBLW, 2048L * XDBLW, 2048, XDBLW, DIN);

    // dt_proj: (2048x64) @ (4096x64)^T (A = first 64 cols of xdbl)
    gemm_mma<<<dim3(DIN / GBN, 2048 / GBM, NHEAD), 256, GSMEM>>>(
        xdbl, XDBLW, 2048L * XDBLW, w_dt, DTRANK, (long)DIN * DTRANK,
        dtb, DIN, 2048L * DIN, 2048, DIN, DTRANK);

    dt_act_kernel<<<cdiv(NHEAD * 2048 * DIN, 256), 256>>>(b_dt);

    scan_kernel<<<dim3(DIN / 8, BATCH, NHEAD), 256>>>(Dp);

    // out_proj: (2048x4096) @ (1024x4096)^T
    gemm_mma<<<dim3(DMODEL / GBN, 2048 / GBM, NHEAD), 256, GSMEM>>>(
        ym, DIN, 2048L * DIN, w_out, DIN, (long)DMODEL * DIN,
        mot, DMODEL, 2048L * DMODEL, 2048, DMODEL, DIN);

    scatter_motion_kernel<<<cdiv(NHEAD * 2 * TMOT * DMODEL, 256), 256>>>(x, out);

    // ---- text path ----
    rms_text_kernel<<<dim3(NTXT, BATCH, NGRP), 256>>>(x, ntw);

    gemm_mma<<<dim3(HID / GBN, 5120 / GBM, 1), 256, GSMEM>>>(
        tn, DMODEL, 0, wg, DMODEL, 0, gb, HID, 0, 5120, HID, DMODEL);
    gemm_mma<<<dim3(HID / GBN, 5120 / GBM, 1), 256, GSMEM>>>(
        tn, DMODEL, 0, wu, DMODEL, 0, ub, HID, 0, 5120, HID, DMODEL);

    silu_gate_kernel<<<cdiv(5120 * HID, 256), 256>>>();

    gemm_mma<<<dim3(DMODEL / GBN, 5120 / GBM, 1), 256, GSMEM>>>(
        gb, HID, 0, wd, HID, 0, txt, DMODEL, 0, 5120, DMODEL, HID);

    scatter_text_kernel<<<cdiv(NGRP * 2 * NTXT * DMODEL, 256), 256>>>(x, out);
}